// round 5
// baseline (speedup 1.0000x reference)
#include <cuda_runtime.h>
#include <cstdint>

// Lightning attention, chunked-parallel, mma.sync tf32 (row.col), cp.async fills.
//   K1: C_j = (k*k_decay)^T @ v                    (2048 CTAs, 64x128x128)
//   K2: in-place exclusive decayed prefix scan of C (-> states S_j)
//   K3a: scores = mask(Q @ K^T)        -> g_SC     (2048 CTAs, 64x128x128)
//   K3b: inter  = qdec * (Q @ S_j)     -> g_I      (2048 CTAs, 64x128x128)
//   K3c: O      = scores @ V + inter               (2048 CTAs, 64x128x128)
// All K1-shaped: 256 thr, single accumulator, ~105 KB smem -> 2 CTAs/SM.

#define SD  136   // smem row stride (words) for 128-col tiles (136%32==8, conflict-free)
#define SDK 72    // smem row stride for K1's 64-col k tile    (72%32==8)

__device__ float g_C [1024u * 16384u];  // 64 MB: chunk KV products -> scanned states
__device__ float g_SC[1024u * 16384u];  // 64 MB: masked decayed scores
__device__ float g_I [1024u * 16384u];  // 64 MB: decayed inter-chunk output

__device__ __forceinline__ uint32_t f2tf(float x){
    uint32_t r; asm("cvt.rna.tf32.f32 %0, %1;" : "=r"(r) : "f"(x)); return r;
}
__device__ __forceinline__ uint32_t s2u(const void* p){
    uint32_t a;
    asm("{ .reg .u64 t; cvta.to.shared.u64 t, %1; cvt.u32.u64 %0, t; }" : "=r"(a) : "l"(p));
    return a;
}
__device__ __forceinline__ void cpa16(uint32_t dst, const void* src){
    asm volatile("cp.async.cg.shared.global [%0], [%1], 16;" :: "r"(dst), "l"(src));
}
#define CP_COMMIT() asm volatile("cp.async.commit_group;" ::: "memory")
#define CP_WAIT0()  asm volatile("cp.async.wait_group 0;" ::: "memory")

__device__ __forceinline__ void mma8(float* c, const uint32_t* a, const uint32_t* b){
    asm volatile(
        "mma.sync.aligned.m16n8k8.row.col.f32.tf32.tf32.f32 "
        "{%0,%1,%2,%3}, {%4,%5,%6,%7}, {%8,%9}, {%0,%1,%2,%3};"
        : "+f"(c[0]), "+f"(c[1]), "+f"(c[2]), "+f"(c[3])
        : "r"(a[0]), "r"(a[1]), "r"(a[2]), "r"(a[3]), "r"(b[0]), "r"(b[1]));
}

// 32x32x128 warp GEMM. AT: element (m,k) at A[k*sa+m]. BT: element (k,n) at B[n*sb+k].
// SC: scale A element (m,k) by kd[k].
template<bool AT, bool SC, bool BT>
__device__ __forceinline__ void gemm32(const float* __restrict__ A, int sa,
                                       const float* __restrict__ B, int sb,
                                       const float* __restrict__ kd,
                                       float acc[2][4][4], int rb, int cb, int lane){
    const int lr = lane >> 2, lc = lane & 3;
#pragma unroll
    for (int ks = 0; ks < 16; ks++){
        const int kc = ks * 8 + lc;
        uint32_t a[2][4];
#pragma unroll
        for (int mt = 0; mt < 2; mt++){
            const int m = rb + mt * 16 + lr;
            float a0, a1, a2, a3;
            if (AT){
                a0 = A[kc * sa + m];       a1 = A[kc * sa + m + 8];
                a2 = A[(kc + 4) * sa + m]; a3 = A[(kc + 4) * sa + m + 8];
            } else {
                a0 = A[m * sa + kc];       a1 = A[(m + 8) * sa + kc];
                a2 = A[m * sa + kc + 4];   a3 = A[(m + 8) * sa + kc + 4];
            }
            if (SC){
                float s0 = kd[kc], s4 = kd[kc + 4];
                a0 *= s0; a1 *= s0; a2 *= s4; a3 *= s4;
            }
            a[mt][0] = f2tf(a0); a[mt][1] = f2tf(a1);
            a[mt][2] = f2tf(a2); a[mt][3] = f2tf(a3);
        }
#pragma unroll
        for (int nt = 0; nt < 4; nt++){
            const int n = cb + nt * 8 + lr;
            float b0v, b1v;
            if (BT){ b0v = B[n * sb + kc];  b1v = B[n * sb + kc + 4]; }
            else   { b0v = B[kc * sb + n];  b1v = B[(kc + 4) * sb + n]; }
            uint32_t b[2] = { f2tf(b0v), f2tf(b1v) };
            mma8(acc[0][nt], a[0], b);
            mma8(acc[1][nt], a[1], b);
        }
    }
}

__device__ __forceinline__ void fill_tile(uint32_t sdst, const float* gsrc, int gstride_f,
                                          int rowbytes, int sstride_b, int rows,
                                          int tid, int nthr){
    const int cpr = rowbytes >> 4;
    const int total = rows * cpr;
    for (int i = tid; i < total; i += nthr){
        int r = i / cpr, c = i - r * cpr;
        cpa16(sdst + r * sstride_b + c * 16, (const char*)gsrc + (size_t)r * gstride_f * 4 + c * 16);
    }
}

// ---------------- K1: C_j = (k * k_decay)^T @ v  (half of d-rows per CTA) ----------------
__global__ void __launch_bounds__(256) k_chunkKV(const float* __restrict__ k,
                                                 const float* __restrict__ v,
                                                 const float* __restrict__ s){
    extern __shared__ float sm[];
    float* kd  = sm;
    float* ksm = sm + 128;
    float* vsm = ksm + 128 * SDK;
    const int tid = threadIdx.x, w = tid >> 5, lane = tid & 31;
    const int g = blockIdx.x >> 1, dh = blockIdx.x & 1, bh = g >> 5;
    const float sh = __ldg(&s[bh & 15]);
    const size_t base = ((size_t)bh * 4096 + (size_t)(g & 31) * 128) * 128;
    const uint32_t sb = s2u(sm);

    fill_tile(sb + 128 * 4, k + base + dh * 64, 128, 256, SDK * 4, 128, tid, 256);
    fill_tile(sb + (128 + 128 * SDK) * 4, v + base, 128, 512, SD * 4, 128, tid, 256);
    CP_COMMIT();
    if (tid < 128) kd[tid] = __expf(-sh * (float)(128 - tid));
    CP_WAIT0();
    __syncthreads();

    const int rb = (w & 1) * 32, cb = (w >> 1) * 32;
    float acc[2][4][4] = {};
    gemm32<true, true, false>(ksm, SDK, vsm, SD, kd, acc, rb, cb, lane);

    float* C = g_C + (size_t)g * 16384 + (size_t)dh * 64 * 128;
    const int lr = lane >> 2, lc2 = (lane & 3) * 2;
#pragma unroll
    for (int mt = 0; mt < 2; mt++){
        const int r = rb + mt * 16 + lr;
#pragma unroll
        for (int nt = 0; nt < 4; nt++){
            const int c = cb + nt * 8 + lc2;
            *(float2*)(C + (size_t)r * 128 + c)       = make_float2(acc[mt][nt][0], acc[mt][nt][1]);
            *(float2*)(C + (size_t)(r + 8) * 128 + c) = make_float2(acc[mt][nt][2], acc[mt][nt][3]);
        }
    }
}

// ---------------- K2: in-place exclusive decayed prefix scan over chunks ----------------
__global__ void __launch_bounds__(256) k_scan(const float* __restrict__ s){
    const int bh = blockIdx.y;
    const int e = blockIdx.x * 256 + threadIdx.x;
    const float lamB = __expf(-__ldg(&s[bh & 15]) * 128.0f);
    float* base = g_C + (size_t)bh * 32 * 16384 + e;
    float val = 0.0f;
#pragma unroll 1
    for (int j = 0; j < 32; j++){
        float c = base[(size_t)j * 16384];
        base[(size_t)j * 16384] = val;
        val = lamB * val + c;
    }
}

// ---------------- K3a: scores = mask(Q @ K^T) -> g_SC ----------------
__global__ void __launch_bounds__(256) k_scores(const float* __restrict__ q,
                                                const float* __restrict__ k,
                                                const float* __restrict__ s){
    extern __shared__ float sm[];
    float* dec = sm;
    float* Qs  = sm + 128;             // 64 x SD
    float* Ks  = Qs + 64 * SD;         // 128 x SD
    const int tid = threadIdx.x, w = tid >> 5, lane = tid & 31;
    const int g = blockIdx.x >> 1, th = blockIdx.x & 1, bh = g >> 5;
    const float sh = __ldg(&s[bh & 15]);
    const size_t base = ((size_t)bh * 4096 + (size_t)(g & 31) * 128) * 128;
    const uint32_t sb = s2u(sm);

    fill_tile(sb + 128 * 4, q + base + (size_t)th * 64 * 128, 128, 512, SD * 4, 64, tid, 256);
    fill_tile(sb + (128 + 64 * SD) * 4, k + base, 128, 512, SD * 4, 128, tid, 256);
    CP_COMMIT();
    if (tid < 128) dec[tid] = __expf(-sh * (float)tid);
    CP_WAIT0();
    __syncthreads();

    const int rb = (w & 1) * 32, cb = (w >> 1) * 32;
    float acc[2][4][4] = {};
    gemm32<false, false, true>(Qs, SD, Ks, SD, nullptr, acc, rb, cb, lane);

    float* SC = g_SC + (size_t)g * 16384 + (size_t)th * 64 * 128;
    const int lr = lane >> 2, lc2 = (lane & 3) * 2;
    const int tofs = th * 64;
#pragma unroll
    for (int mt = 0; mt < 2; mt++){
        const int r = rb + mt * 16 + lr;
        const int rg = tofs + r;
#pragma unroll
        for (int nt = 0; nt < 4; nt++){
            const int c = cb + nt * 8 + lc2;
            float v00 = (rg     >= c    ) ? acc[mt][nt][0] * dec[rg - c]     : 0.0f;
            float v01 = (rg     >= c + 1) ? acc[mt][nt][1] * dec[rg - c - 1] : 0.0f;
            float v10 = (rg + 8 >= c    ) ? acc[mt][nt][2] * dec[rg + 8 - c] : 0.0f;
            float v11 = (rg + 8 >= c + 1) ? acc[mt][nt][3] * dec[rg + 7 - c] : 0.0f;
            *(float2*)(SC + (size_t)r * 128 + c)       = make_float2(v00, v01);
            *(float2*)(SC + (size_t)(r + 8) * 128 + c) = make_float2(v10, v11);
        }
    }
}

// ---------------- K3b: inter = qdec * (Q @ S_j) -> g_I ----------------
__global__ void __launch_bounds__(256) k_inter(const float* __restrict__ q,
                                               const float* __restrict__ s){
    extern __shared__ float sm[];
    float* dec = sm;
    float* Qs  = sm + 128;
    float* Ss  = Qs + 64 * SD;
    const int tid = threadIdx.x, w = tid >> 5, lane = tid & 31;
    const int g = blockIdx.x >> 1, th = blockIdx.x & 1, bh = g >> 5;
    const float sh = __ldg(&s[bh & 15]);
    const size_t base = ((size_t)bh * 4096 + (size_t)(g & 31) * 128) * 128;
    const uint32_t sb = s2u(sm);

    fill_tile(sb + 128 * 4, q + base + (size_t)th * 64 * 128, 128, 512, SD * 4, 64, tid, 256);
    fill_tile(sb + (128 + 64 * SD) * 4, g_C + (size_t)g * 16384, 128, 512, SD * 4, 128, tid, 256);
    CP_COMMIT();
    if (tid < 128) dec[tid] = __expf(-sh * (float)tid);
    CP_WAIT0();
    __syncthreads();

    const int rb = (w & 1) * 32, cb = (w >> 1) * 32;
    float acc[2][4][4] = {};
    gemm32<false, false, false>(Qs, SD, Ss, SD, nullptr, acc, rb, cb, lane);

    float* I = g_I + (size_t)g * 16384 + (size_t)th * 64 * 128;
    const int lr = lane >> 2, lc2 = (lane & 3) * 2;
    const int tofs = th * 64;
#pragma unroll
    for (int mt = 0; mt < 2; mt++){
        const int r = rb + mt * 16 + lr;
        const float e0 = dec[tofs + r], e8 = dec[tofs + r + 8];
#pragma unroll
        for (int nt = 0; nt < 4; nt++){
            const int c = cb + nt * 8 + lc2;
            *(float2*)(I + (size_t)r * 128 + c)       = make_float2(acc[mt][nt][0] * e0, acc[mt][nt][1] * e0);
            *(float2*)(I + (size_t)(r + 8) * 128 + c) = make_float2(acc[mt][nt][2] * e8, acc[mt][nt][3] * e8);
        }
    }
}

// ---------------- K3c: O = scores @ V + inter ----------------
__global__ void __launch_bounds__(256) k_combine(const float* __restrict__ v,
                                                 float* __restrict__ o){
    extern __shared__ float sm[];
    float* Ps = sm;                    // scores 64 x SD
    float* Vs = Ps + 64 * SD;          // V 128 x SD
    const int tid = threadIdx.x, w = tid >> 5, lane = tid & 31;
    const int g = blockIdx.x >> 1, th = blockIdx.x & 1, bh = g >> 5;
    const size_t base = ((size_t)bh * 4096 + (size_t)(g & 31) * 128) * 128;
    const uint32_t sb = s2u(sm);

    fill_tile(sb, g_SC + (size_t)g * 16384 + (size_t)th * 64 * 128, 128, 512, SD * 4, 64, tid, 256);
    fill_tile(sb + 64 * SD * 4, v + base, 128, 512, SD * 4, 128, tid, 256);
    CP_COMMIT();
    CP_WAIT0();
    __syncthreads();

    const int rb = (w & 1) * 32, cb = (w >> 1) * 32;
    float acc[2][4][4] = {};
    gemm32<false, false, false>(Ps, SD, Vs, SD, nullptr, acc, rb, cb, lane);

    const float* I = g_I + (size_t)g * 16384 + (size_t)th * 64 * 128;
    float* O = o + base + (size_t)th * 64 * 128;
    const int lr = lane >> 2, lc2 = (lane & 3) * 2;
#pragma unroll
    for (int mt = 0; mt < 2; mt++){
        const int r = rb + mt * 16 + lr;
#pragma unroll
        for (int nt = 0; nt < 4; nt++){
            const int c = cb + nt * 8 + lc2;
            float2 i0 = *(const float2*)(I + (size_t)r * 128 + c);
            float2 i1 = *(const float2*)(I + (size_t)(r + 8) * 128 + c);
            *(float2*)(O + (size_t)r * 128 + c)       = make_float2(acc[mt][nt][0] + i0.x, acc[mt][nt][1] + i0.y);
            *(float2*)(O + (size_t)(r + 8) * 128 + c) = make_float2(acc[mt][nt][2] + i1.x, acc[mt][nt][3] + i1.y);
        }
    }
}

extern "C" void kernel_launch(void* const* d_in, const int* in_sizes, int n_in,
                              void* d_out, int out_size) {
    const float* q = (const float*)d_in[0];
    const float* k = (const float*)d_in[1];
    const float* v = (const float*)d_in[2];
    const float* s = (const float*)d_in[3];
    float* o = (float*)d_out;

    const int sm1 = (128 + 128 * SDK + 128 * SD) * 4;        // 107,008 B
    const int smQ = (128 + 64 * SD + 128 * SD) * 4;          // 105,008 B
    const int smC = (64 * SD + 128 * SD) * 4;                //  (no dec table)
    cudaFuncSetAttribute(k_chunkKV, cudaFuncAttributeMaxDynamicSharedMemorySize, sm1);
    cudaFuncSetAttribute(k_scores,  cudaFuncAttributeMaxDynamicSharedMemorySize, smQ);
    cudaFuncSetAttribute(k_inter,   cudaFuncAttributeMaxDynamicSharedMemorySize, smQ);
    cudaFuncSetAttribute(k_combine, cudaFuncAttributeMaxDynamicSharedMemorySize, smC);

    k_chunkKV<<<2048, 256, sm1>>>(k, v, s);
    k_scores <<<2048, 256, smQ>>>(q, k, s);
    k_scan   <<<dim3(64, 32), 256>>>(s);
    k_inter  <<<2048, 256, smQ>>>(q, s);
    k_combine<<<2048, 256, smC>>>(v, o);
}

// round 6
// speedup vs baseline: 4.4431x; 4.4431x over previous
#include <cuda_runtime.h>
#include <cstdint>

// Lightning attention, chunked-parallel, mma.sync tf32 (row.col), cp.async fills.
//   K1: C_j = (k*k_decay)^T @ v                 (2048 CTAs, 64x128x128)
//   K2: exclusive decayed prefix scan g_C -> g_S (separate streams, float4, prefetch)
//   K3: scores=(Q K^T)*mask; O = qdec*(Q@S) + scores@V  (monolithic, 3 GEMMs/CTA)

#define SD  136   // smem row stride (words) for 128-col tiles (136%32==8, conflict-free)
#define SDK 72    // smem row stride for K1's 64-col k tile    (72%32==8)

__device__ float g_C[1024u * 16384u];   // 64 MB: chunk KV products (read-only after K1)
__device__ float g_S[1024u * 16384u];   // 64 MB: scanned exclusive states

__device__ __forceinline__ uint32_t f2tf(float x){
    uint32_t r; asm("cvt.rna.tf32.f32 %0, %1;" : "=r"(r) : "f"(x)); return r;
}
__device__ __forceinline__ uint32_t s2u(const void* p){
    uint32_t a;
    asm("{ .reg .u64 t; cvta.to.shared.u64 t, %1; cvt.u32.u64 %0, t; }" : "=r"(a) : "l"(p));
    return a;
}
__device__ __forceinline__ void cpa16(uint32_t dst, const void* src){
    asm volatile("cp.async.cg.shared.global [%0], [%1], 16;" :: "r"(dst), "l"(src));
}
#define CP_COMMIT() asm volatile("cp.async.commit_group;" ::: "memory")
#define CP_WAIT0()  asm volatile("cp.async.wait_group 0;" ::: "memory")

__device__ __forceinline__ void mma8(float* c, const uint32_t* a, const uint32_t* b){
    asm volatile(
        "mma.sync.aligned.m16n8k8.row.col.f32.tf32.tf32.f32 "
        "{%0,%1,%2,%3}, {%4,%5,%6,%7}, {%8,%9}, {%0,%1,%2,%3};"
        : "+f"(c[0]), "+f"(c[1]), "+f"(c[2]), "+f"(c[3])
        : "r"(a[0]), "r"(a[1]), "r"(a[2]), "r"(a[3]), "r"(b[0]), "r"(b[1]));
}

// 32x32x128 warp GEMM. AT: element (m,k) at A[k*sa+m]. BT: element (k,n) at B[n*sb+k].
// SC: scale A element (m,k) by kd[k].
template<bool AT, bool SC, bool BT>
__device__ __forceinline__ void gemm32(const float* __restrict__ A, int sa,
                                       const float* __restrict__ B, int sb,
                                       const float* __restrict__ kd,
                                       float acc[2][4][4], int rb, int cb, int lane){
    const int lr = lane >> 2, lc = lane & 3;
#pragma unroll
    for (int ks = 0; ks < 16; ks++){
        const int kc = ks * 8 + lc;
        uint32_t a[2][4];
#pragma unroll
        for (int mt = 0; mt < 2; mt++){
            const int m = rb + mt * 16 + lr;
            float a0, a1, a2, a3;
            if (AT){
                a0 = A[kc * sa + m];       a1 = A[kc * sa + m + 8];
                a2 = A[(kc + 4) * sa + m]; a3 = A[(kc + 4) * sa + m + 8];
            } else {
                a0 = A[m * sa + kc];       a1 = A[(m + 8) * sa + kc];
                a2 = A[m * sa + kc + 4];   a3 = A[(m + 8) * sa + kc + 4];
            }
            if (SC){
                float s0 = kd[kc], s4 = kd[kc + 4];
                a0 *= s0; a1 *= s0; a2 *= s4; a3 *= s4;
            }
            a[mt][0] = f2tf(a0); a[mt][1] = f2tf(a1);
            a[mt][2] = f2tf(a2); a[mt][3] = f2tf(a3);
        }
#pragma unroll
        for (int nt = 0; nt < 4; nt++){
            const int n = cb + nt * 8 + lr;
            float b0v, b1v;
            if (BT){ b0v = B[n * sb + kc];  b1v = B[n * sb + kc + 4]; }
            else   { b0v = B[kc * sb + n];  b1v = B[(kc + 4) * sb + n]; }
            uint32_t b[2] = { f2tf(b0v), f2tf(b1v) };
            mma8(acc[0][nt], a[0], b);
            mma8(acc[1][nt], a[1], b);
        }
    }
}

__device__ __forceinline__ void fill_tile(uint32_t sdst, const float* gsrc, int gstride_f,
                                          int rowbytes, int sstride_b, int rows,
                                          int tid, int nthr){
    const int cpr = rowbytes >> 4;
    const int total = rows * cpr;
    for (int i = tid; i < total; i += nthr){
        int r = i / cpr, c = i - r * cpr;
        cpa16(sdst + r * sstride_b + c * 16, (const char*)gsrc + (size_t)r * gstride_f * 4 + c * 16);
    }
}

// ---------------- K1: C_j = (k * k_decay)^T @ v  (half of d-rows per CTA) ----------------
__global__ void __launch_bounds__(256) k_chunkKV(const float* __restrict__ k,
                                                 const float* __restrict__ v,
                                                 const float* __restrict__ s){
    extern __shared__ float sm[];
    float* kd  = sm;
    float* ksm = sm + 128;
    float* vsm = ksm + 128 * SDK;
    const int tid = threadIdx.x, w = tid >> 5, lane = tid & 31;
    const int g = blockIdx.x >> 1, dh = blockIdx.x & 1, bh = g >> 5;
    const float sh = __ldg(&s[bh & 15]);
    const size_t base = ((size_t)bh * 4096 + (size_t)(g & 31) * 128) * 128;
    const uint32_t sb = s2u(sm);

    fill_tile(sb + 128 * 4, k + base + dh * 64, 128, 256, SDK * 4, 128, tid, 256);
    fill_tile(sb + (128 + 128 * SDK) * 4, v + base, 128, 512, SD * 4, 128, tid, 256);
    CP_COMMIT();
    if (tid < 128) kd[tid] = __expf(-sh * (float)(128 - tid));
    CP_WAIT0();
    __syncthreads();

    const int rb = (w & 1) * 32, cb = (w >> 1) * 32;
    float acc[2][4][4] = {};
    gemm32<true, true, false>(ksm, SDK, vsm, SD, kd, acc, rb, cb, lane);

    float* C = g_C + (size_t)g * 16384 + (size_t)dh * 64 * 128;
    const int lr = lane >> 2, lc2 = (lane & 3) * 2;
#pragma unroll
    for (int mt = 0; mt < 2; mt++){
        const int r = rb + mt * 16 + lr;
#pragma unroll
        for (int nt = 0; nt < 4; nt++){
            const int c = cb + nt * 8 + lc2;
            *(float2*)(C + (size_t)r * 128 + c)       = make_float2(acc[mt][nt][0], acc[mt][nt][1]);
            *(float2*)(C + (size_t)(r + 8) * 128 + c) = make_float2(acc[mt][nt][2], acc[mt][nt][3]);
        }
    }
}

// ---------------- K2: exclusive decayed prefix scan, g_C -> g_S ----------------
// Pure streams (no same-address hazard), float4 per thread, next-j prefetch.
__global__ void __launch_bounds__(256) k_scan(const float* __restrict__ s){
    const int bh = blockIdx.y;
    const int e4 = blockIdx.x * 256 + threadIdx.x;          // float4 index within 16384
    const float lamB = __expf(-__ldg(&s[bh & 15]) * 128.0f);
    const float4* __restrict__ src = (const float4*)(g_C + (size_t)bh * 32 * 16384) + e4;
    float4* __restrict__ dst       = (float4*)(g_S + (size_t)bh * 32 * 16384) + e4;

    float4 val = make_float4(0.f, 0.f, 0.f, 0.f);
    float4 c = src[0];
#pragma unroll
    for (int j = 0; j < 32; j++){
        float4 cn = (j < 31) ? src[(j + 1) * 4096] : make_float4(0.f, 0.f, 0.f, 0.f);
        dst[j * 4096] = val;
        val.x = lamB * val.x + c.x;
        val.y = lamB * val.y + c.y;
        val.z = lamB * val.z + c.z;
        val.w = lamB * val.w + c.w;
        c = cn;
    }
}

// ---------------- K3: output (monolithic, as in round 4) ----------------
__global__ void __launch_bounds__(512) k_output(const float* __restrict__ q,
                                                const float* __restrict__ k,
                                                const float* __restrict__ v,
                                                const float* __restrict__ s,
                                                float* __restrict__ o){
    extern __shared__ float sm[];
    float* dec  = sm;
    float* Qs   = sm + 128;
    float* buf1 = Qs + 128 * SD;         // K, then scores
    float* buf2 = buf1 + 128 * SD;       // S, then V
    const int tid = threadIdx.x, w = tid >> 5, lane = tid & 31;
    const int g = blockIdx.x, bh = g >> 5;
    const float sh = __ldg(&s[bh & 15]);
    const size_t base = ((size_t)bh * 4096 + (size_t)(g & 31) * 128) * 128;
    const uint32_t sb = s2u(sm);
    const uint32_t oQ = sb + 128 * 4, o1 = oQ + 128 * SD * 4, o2 = o1 + 128 * SD * 4;
    const float* S = g_S + (size_t)g * 16384;

    fill_tile(oQ, q + base, 128, 512, SD * 4, 128, tid, 512);
    fill_tile(o1, k + base, 128, 512, SD * 4, 128, tid, 512);
    fill_tile(o2, S, 128, 512, SD * 4, 128, tid, 512);
    CP_COMMIT();
    if (tid < 128) dec[tid] = __expf(-sh * (float)tid);
    CP_WAIT0();
    __syncthreads();

    const int rb = (w >> 2) * 32, cb = (w & 3) * 32;
    const int lr = lane >> 2, lc2 = (lane & 3) * 2;

    float acc1[2][4][4] = {};   // scores = Q @ K^T
    gemm32<false, false, true >(Qs, SD, buf1, SD, nullptr, acc1, rb, cb, lane);
    float acc2[2][4][4] = {};   // inter = Q @ S
    gemm32<false, false, false>(Qs, SD, buf2, SD, nullptr, acc2, rb, cb, lane);
    __syncthreads();            // done reading buf1 (K) and buf2 (S)

    // start V copy into buf2; overlaps the epilogue below
    fill_tile(o2, v + base, 128, 512, SD * 4, 128, tid, 512);
    CP_COMMIT();

    // epilogue: mask+decay scores -> buf1 (fp32); pre-scale inter by q_decay
#pragma unroll
    for (int mt = 0; mt < 2; mt++){
        const int r = rb + mt * 16 + lr;
        const float e0 = dec[r], e8 = dec[r + 8];
#pragma unroll
        for (int nt = 0; nt < 4; nt++){
            const int c = cb + nt * 8 + lc2;
            float v00 = (r     >= c    ) ? acc1[mt][nt][0] * dec[r - c]     : 0.0f;
            float v01 = (r     >= c + 1) ? acc1[mt][nt][1] * dec[r - c - 1] : 0.0f;
            float v10 = (r + 8 >= c    ) ? acc1[mt][nt][2] * dec[r + 8 - c] : 0.0f;
            float v11 = (r + 8 >= c + 1) ? acc1[mt][nt][3] * dec[r + 7 - c] : 0.0f;
            *(float2*)(buf1 + r * SD + c)       = make_float2(v00, v01);
            *(float2*)(buf1 + (r + 8) * SD + c) = make_float2(v10, v11);
            acc2[mt][nt][0] *= e0; acc2[mt][nt][1] *= e0;
            acc2[mt][nt][2] *= e8; acc2[mt][nt][3] *= e8;
        }
    }
    CP_WAIT0();
    __syncthreads();

    // out = qdec*(Q@S) + scores @ V
    gemm32<false, false, false>(buf1, SD, buf2, SD, nullptr, acc2, rb, cb, lane);

#pragma unroll
    for (int mt = 0; mt < 2; mt++){
        const int r = rb + mt * 16 + lr;
#pragma unroll
        for (int nt = 0; nt < 4; nt++){
            const int c = cb + nt * 8 + lc2;
            *(float2*)(o + base + (size_t)r * 128 + c)       = make_float2(acc2[mt][nt][0], acc2[mt][nt][1]);
            *(float2*)(o + base + (size_t)(r + 8) * 128 + c) = make_float2(acc2[mt][nt][2], acc2[mt][nt][3]);
        }
    }
}

extern "C" void kernel_launch(void* const* d_in, const int* in_sizes, int n_in,
                              void* d_out, int out_size) {
    const float* q = (const float*)d_in[0];
    const float* k = (const float*)d_in[1];
    const float* v = (const float*)d_in[2];
    const float* s = (const float*)d_in[3];
    float* o = (float*)d_out;

    const int sm1 = (128 + 128 * SDK + 128 * SD) * 4;       // 107,008 B
    const int sm3 = (128 + 3 * 128 * SD) * 4;               // 209,408 B
    cudaFuncSetAttribute(k_chunkKV, cudaFuncAttributeMaxDynamicSharedMemorySize, sm1);
    cudaFuncSetAttribute(k_output,  cudaFuncAttributeMaxDynamicSharedMemorySize, sm3);

    k_chunkKV<<<2048, 256, sm1>>>(k, v, s);
    k_scan<<<dim3(16, 32), 256>>>(s);
    k_output<<<1024, 512, sm3>>>(q, k, v, s, o);
}

// round 7
// speedup vs baseline: 4.5742x; 1.0295x over previous
#include <cuda_runtime.h>
#include <cstdint>

// Lightning attention, chunked-parallel, mma.sync tf32 (row.col), cp.async fills,
// in-place tf32 pre-conversion of smem tiles (cvt once per element, raw fragment loads).
//   K1: C_j = (k*k_decay)^T @ v                 (2048 CTAs, 64x128x128)
//   K2: exclusive decayed prefix scan g_C -> g_S (pure streams, float4, prefetch)
//   K3: scores=(Q K^T)*mask; O = qdec*(Q@S) + scores@V  (3 GEMMs/CTA, overlapped fills)

#define SD  136   // smem row stride (words) for 128-col tiles (136%32==8, conflict-free)
#define SDK 72    // smem row stride for K1's 64-col k tile    (72%32==8)

__device__ float g_C[1024u * 16384u];   // 64 MB: chunk KV products
__device__ float g_S[1024u * 16384u];   // 64 MB: scanned exclusive states

__device__ __forceinline__ uint32_t f2tf(float x){
    uint32_t r; asm("cvt.rna.tf32.f32 %0, %1;" : "=r"(r) : "f"(x)); return r;
}
__device__ __forceinline__ uint32_t s2u(const void* p){
    uint32_t a;
    asm("{ .reg .u64 t; cvta.to.shared.u64 t, %1; cvt.u32.u64 %0, t; }" : "=r"(a) : "l"(p));
    return a;
}
__device__ __forceinline__ void cpa16(uint32_t dst, const void* src){
    asm volatile("cp.async.cg.shared.global [%0], [%1], 16;" :: "r"(dst), "l"(src));
}
#define CP_COMMIT() asm volatile("cp.async.commit_group;" ::: "memory")
#define CP_WAIT0()  asm volatile("cp.async.wait_group 0;" ::: "memory")
#define CP_WAIT1()  asm volatile("cp.async.wait_group 1;" ::: "memory")

__device__ __forceinline__ void mma8(float* c, const uint32_t* a, const uint32_t* b){
    asm volatile(
        "mma.sync.aligned.m16n8k8.row.col.f32.tf32.tf32.f32 "
        "{%0,%1,%2,%3}, {%4,%5,%6,%7}, {%8,%9}, {%0,%1,%2,%3};"
        : "+f"(c[0]), "+f"(c[1]), "+f"(c[2]), "+f"(c[3])
        : "r"(a[0]), "r"(a[1]), "r"(a[2]), "r"(a[3]), "r"(b[0]), "r"(b[1]));
}

// 32x32x128 warp GEMM on PRE-CONVERTED tf32 tiles (raw uint32 loads, no cvt/scale).
// AT: element (m,k) at A[k*sa+m]. BT: element (k,n) at B[n*sb+k].
template<bool AT, bool BT>
__device__ __forceinline__ void gemm32r(const uint32_t* __restrict__ A, int sa,
                                        const uint32_t* __restrict__ B, int sb,
                                        float acc[2][4][4], int rb, int cb, int lane){
    const int lr = lane >> 2, lc = lane & 3;
#pragma unroll
    for (int ks = 0; ks < 16; ks++){
        const int kc = ks * 8 + lc;
        uint32_t a[2][4];
#pragma unroll
        for (int mt = 0; mt < 2; mt++){
            const int m = rb + mt * 16 + lr;
            if (AT){
                a[mt][0] = A[kc * sa + m];       a[mt][1] = A[kc * sa + m + 8];
                a[mt][2] = A[(kc + 4) * sa + m]; a[mt][3] = A[(kc + 4) * sa + m + 8];
            } else {
                a[mt][0] = A[m * sa + kc];       a[mt][1] = A[(m + 8) * sa + kc];
                a[mt][2] = A[m * sa + kc + 4];   a[mt][3] = A[(m + 8) * sa + kc + 4];
            }
        }
#pragma unroll
        for (int nt = 0; nt < 4; nt++){
            const int n = cb + nt * 8 + lr;
            uint32_t b[2];
            if (BT){ b[0] = B[n * sb + kc];  b[1] = B[n * sb + kc + 4]; }
            else   { b[0] = B[kc * sb + n];  b[1] = B[(kc + 4) * sb + n]; }
            mma8(acc[0][nt], a[0], b);
            mma8(acc[1][nt], a[1], b);
        }
    }
}

__device__ __forceinline__ void fill_tile(uint32_t sdst, const float* gsrc, int gstride_f,
                                          int rowbytes, int sstride_b, int rows,
                                          int tid, int nthr){
    const int cpr = rowbytes >> 4;
    const int total = rows * cpr;
    for (int i = tid; i < total; i += nthr){
        int r = i / cpr, c = i - r * cpr;
        cpa16(sdst + r * sstride_b + c * 16, (const char*)gsrc + (size_t)r * gstride_f * 4 + c * 16);
    }
}

// In-place fp32 -> tf32 (rna) conversion of a tile; f4pr = valid float4s per row.
__device__ __forceinline__ void cvt_tile(float* t, int stride, int rows, int f4pr,
                                         int tid, int nthr){
    const int total = rows * f4pr;
    for (int i = tid; i < total; i += nthr){
        int r = i / f4pr, c4 = (i - r * f4pr) * 4;
        float4* p = (float4*)(t + r * stride + c4);
        float4 v = *p;
        *(uint4*)p = make_uint4(f2tf(v.x), f2tf(v.y), f2tf(v.z), f2tf(v.w));
    }
}
// Same, with per-row scale folded in (K1 decay).
__device__ __forceinline__ void cvt_tile_scaled(float* t, int stride, int rows, int f4pr,
                                                const float* rs, int tid, int nthr){
    const int total = rows * f4pr;
    for (int i = tid; i < total; i += nthr){
        int r = i / f4pr, c4 = (i - r * f4pr) * 4;
        float4* p = (float4*)(t + r * stride + c4);
        float4 v = *p;
        const float sc = rs[r];
        *(uint4*)p = make_uint4(f2tf(v.x * sc), f2tf(v.y * sc), f2tf(v.z * sc), f2tf(v.w * sc));
    }
}

// ---------------- K1: C_j = (k * k_decay)^T @ v  (half of d-rows per CTA) ----------------
__global__ void __launch_bounds__(256) k_chunkKV(const float* __restrict__ k,
                                                 const float* __restrict__ v,
                                                 const float* __restrict__ s){
    extern __shared__ float sm[];
    float* kd  = sm;
    float* ksm = sm + 128;               // [tau][d-half], SDK stride
    float* vsm = ksm + 128 * SDK;        // [tau][e], SD stride
    const int tid = threadIdx.x, w = tid >> 5, lane = tid & 31;
    const int g = blockIdx.x >> 1, dh = blockIdx.x & 1, bh = g >> 5;
    const float sh = __ldg(&s[bh & 15]);
    const size_t base = ((size_t)bh * 4096 + (size_t)(g & 31) * 128) * 128;
    const uint32_t sb = s2u(sm);

    fill_tile(sb + 128 * 4, k + base + dh * 64, 128, 256, SDK * 4, 128, tid, 256);
    fill_tile(sb + (128 + 128 * SDK) * 4, v + base, 128, 512, SD * 4, 128, tid, 256);
    CP_COMMIT();
    if (tid < 128) kd[tid] = __expf(-sh * (float)(128 - tid));
    CP_WAIT0();
    __syncthreads();

    cvt_tile_scaled(ksm, SDK, 128, 16, kd, tid, 256);   // fold decay + cvt once
    cvt_tile(vsm, SD, 128, 32, tid, 256);
    __syncthreads();

    const int rb = (w & 1) * 32, cb = (w >> 1) * 32;
    float acc[2][4][4] = {};
    gemm32r<true, false>((const uint32_t*)ksm, SDK, (const uint32_t*)vsm, SD, acc, rb, cb, lane);

    float* C = g_C + (size_t)g * 16384 + (size_t)dh * 64 * 128;
    const int lr = lane >> 2, lc2 = (lane & 3) * 2;
#pragma unroll
    for (int mt = 0; mt < 2; mt++){
        const int r = rb + mt * 16 + lr;
#pragma unroll
        for (int nt = 0; nt < 4; nt++){
            const int c = cb + nt * 8 + lc2;
            *(float2*)(C + (size_t)r * 128 + c)       = make_float2(acc[mt][nt][0], acc[mt][nt][1]);
            *(float2*)(C + (size_t)(r + 8) * 128 + c) = make_float2(acc[mt][nt][2], acc[mt][nt][3]);
        }
    }
}

// ---------------- K2: exclusive decayed prefix scan, g_C -> g_S ----------------
__global__ void __launch_bounds__(256) k_scan(const float* __restrict__ s){
    const int bh = blockIdx.y;
    const int e4 = blockIdx.x * 256 + threadIdx.x;
    const float lamB = __expf(-__ldg(&s[bh & 15]) * 128.0f);
    const float4* __restrict__ src = (const float4*)(g_C + (size_t)bh * 32 * 16384) + e4;
    float4* __restrict__ dst       = (float4*)(g_S + (size_t)bh * 32 * 16384) + e4;

    float4 val = make_float4(0.f, 0.f, 0.f, 0.f);
    float4 c = src[0];
#pragma unroll
    for (int j = 0; j < 32; j++){
        float4 cn = (j < 31) ? src[(j + 1) * 4096] : make_float4(0.f, 0.f, 0.f, 0.f);
        dst[j * 4096] = val;
        val.x = lamB * val.x + c.x;
        val.y = lamB * val.y + c.y;
        val.z = lamB * val.z + c.z;
        val.w = lamB * val.w + c.w;
        c = cn;
    }
}

// ---------------- K3: output (3 GEMMs, overlapped fills, pre-cvt tiles) ----------------
__global__ void __launch_bounds__(512) k_output(const float* __restrict__ q,
                                                const float* __restrict__ k,
                                                const float* __restrict__ v,
                                                const float* __restrict__ s,
                                                float* __restrict__ o){
    extern __shared__ float sm[];
    float* dec  = sm;
    float* Qs   = sm + 128;              // Q, later V
    float* buf1 = Qs + 128 * SD;         // K, later scores
    float* buf2 = buf1 + 128 * SD;       // S
    const int tid = threadIdx.x, w = tid >> 5, lane = tid & 31;
    const int g = blockIdx.x, bh = g >> 5;
    const float sh = __ldg(&s[bh & 15]);
    const size_t base = ((size_t)bh * 4096 + (size_t)(g & 31) * 128) * 128;
    const uint32_t sb = s2u(sm);
    const uint32_t oQ = sb + 128 * 4, o1 = oQ + 128 * SD * 4, o2 = o1 + 128 * SD * 4;

    fill_tile(oQ, q + base, 128, 512, SD * 4, 128, tid, 512);
    fill_tile(o1, k + base, 128, 512, SD * 4, 128, tid, 512);
    CP_COMMIT();                                          // group: Q+K
    fill_tile(o2, g_S + (size_t)g * 16384, 128, 512, SD * 4, 128, tid, 512);
    CP_COMMIT();                                          // group: S (lands during GEMM1)
    if (tid < 128) dec[tid] = __expf(-sh * (float)tid);
    CP_WAIT1();                                           // Q+K ready (S may be in flight)
    __syncthreads();

    cvt_tile(Qs, SD, 128, 32, tid, 512);
    cvt_tile(buf1, SD, 128, 32, tid, 512);
    __syncthreads();

    const int rb = (w >> 2) * 32, cb = (w & 3) * 32;
    const int lr = lane >> 2, lc2 = (lane & 3) * 2;

    float acc1[2][4][4] = {};   // scores = Q @ K^T
    gemm32r<false, true>((const uint32_t*)Qs, SD, (const uint32_t*)buf1, SD, acc1, rb, cb, lane);

    CP_WAIT0();                 // S arrived (overlapped with GEMM1)
    cvt_tile(buf2, SD, 128, 32, tid, 512);
    __syncthreads();            // S converted; all warps past GEMM1

    float acc2[2][4][4] = {};   // inter = Q @ S
    gemm32r<false, false>((const uint32_t*)Qs, SD, (const uint32_t*)buf2, SD, acc2, rb, cb, lane);
    __syncthreads();            // all done reading Qs (Q dead)

    // V load into Qs overlaps the epilogue below
    fill_tile(oQ, v + base, 128, 512, SD * 4, 128, tid, 512);
    CP_COMMIT();

    // epilogue: mask+decay scores -> buf1 as tf32; pre-scale inter by q_decay
    uint32_t* sc = (uint32_t*)buf1;
#pragma unroll
    for (int mt = 0; mt < 2; mt++){
        const int r = rb + mt * 16 + lr;
        const float e0 = dec[r], e8 = dec[r + 8];
#pragma unroll
        for (int nt = 0; nt < 4; nt++){
            const int c = cb + nt * 8 + lc2;
            uint32_t v00 = f2tf((r     >= c    ) ? acc1[mt][nt][0] * dec[r - c]     : 0.0f);
            uint32_t v01 = f2tf((r     >= c + 1) ? acc1[mt][nt][1] * dec[r - c - 1] : 0.0f);
            uint32_t v10 = f2tf((r + 8 >= c    ) ? acc1[mt][nt][2] * dec[r + 8 - c] : 0.0f);
            uint32_t v11 = f2tf((r + 8 >= c + 1) ? acc1[mt][nt][3] * dec[r + 7 - c] : 0.0f);
            *(uint2*)(sc + r * SD + c)       = make_uint2(v00, v01);
            *(uint2*)(sc + (r + 8) * SD + c) = make_uint2(v10, v11);
            acc2[mt][nt][0] *= e0; acc2[mt][nt][1] *= e0;
            acc2[mt][nt][2] *= e8; acc2[mt][nt][3] *= e8;
        }
    }
    CP_WAIT0();
    __syncthreads();            // V in, scores written

    cvt_tile(Qs, SD, 128, 32, tid, 512);   // V -> tf32
    __syncthreads();

    // out = qdec*(Q@S) + scores @ V
    gemm32r<false, false>((const uint32_t*)buf1, SD, (const uint32_t*)Qs, SD, acc2, rb, cb, lane);

#pragma unroll
    for (int mt = 0; mt < 2; mt++){
        const int r = rb + mt * 16 + lr;
#pragma unroll
        for (int nt = 0; nt < 4; nt++){
            const int c = cb + nt * 8 + lc2;
            *(float2*)(o + base + (size_t)r * 128 + c)       = make_float2(acc2[mt][nt][0], acc2[mt][nt][1]);
            *(float2*)(o + base + (size_t)(r + 8) * 128 + c) = make_float2(acc2[mt][nt][2], acc2[mt][nt][3]);
        }
    }
}

extern "C" void kernel_launch(void* const* d_in, const int* in_sizes, int n_in,
                              void* d_out, int out_size) {
    const float* q = (const float*)d_in[0];
    const float* k = (const float*)d_in[1];
    const float* v = (const float*)d_in[2];
    const float* s = (const float*)d_in[3];
    float* o = (float*)d_out;

    const int sm1 = (128 + 128 * SDK + 128 * SD) * 4;       // 107,008 B
    const int sm3 = (128 + 3 * 128 * SD) * 4;               // 209,408 B
    cudaFuncSetAttribute(k_chunkKV, cudaFuncAttributeMaxDynamicSharedMemorySize, sm1);
    cudaFuncSetAttribute(k_output,  cudaFuncAttributeMaxDynamicSharedMemorySize, sm3);

    k_chunkKV<<<2048, 256, sm1>>>(k, v, s);
    k_scan<<<dim3(16, 32), 256>>>(s);
    k_output<<<1024, 512, sm3>>>(q, k, v, s, o);
}

// round 8
// speedup vs baseline: 4.8882x; 1.0686x over previous
#include <cuda_runtime.h>
#include <cstdint>

// Lightning attention, chunked-parallel, mma.sync tf32 (row.col), cp.async fills.
//   K1: C_j = (k*k_decay)^T @ v   (2048 CTAs, 64x128x128, inline cvt+scale in GEMM)
//   K2: exclusive decayed prefix scan g_C -> g_S (pure streams, float4; S stored tf32)
//   K3: O = qdec*(Q@S) + (mask(Q K^T))@V   (GEMM2 first; K,V fills overlapped)

#define SD  136   // smem row stride (words) for 128-col tiles (136%32==8, conflict-free)
#define SDK 72    // smem row stride for K1's 64-col k tile    (72%32==8)

__device__ float g_C[1024u * 16384u];   // 64 MB: chunk KV products
__device__ float g_S[1024u * 16384u];   // 64 MB: scanned exclusive states (tf32 bits)

__device__ __forceinline__ uint32_t f2tf(float x){
    uint32_t r; asm("cvt.rna.tf32.f32 %0, %1;" : "=r"(r) : "f"(x)); return r;
}
__device__ __forceinline__ uint32_t s2u(const void* p){
    uint32_t a;
    asm("{ .reg .u64 t; cvta.to.shared.u64 t, %1; cvt.u32.u64 %0, t; }" : "=r"(a) : "l"(p));
    return a;
}
__device__ __forceinline__ void cpa16(uint32_t dst, const void* src){
    asm volatile("cp.async.cg.shared.global [%0], [%1], 16;" :: "r"(dst), "l"(src));
}
#define CP_COMMIT() asm volatile("cp.async.commit_group;" ::: "memory")
#define CP_WAIT0()  asm volatile("cp.async.wait_group 0;" ::: "memory")
#define CP_WAIT1()  asm volatile("cp.async.wait_group 1;" ::: "memory")

__device__ __forceinline__ void mma8(float* c, const uint32_t* a, const uint32_t* b){
    asm volatile(
        "mma.sync.aligned.m16n8k8.row.col.f32.tf32.tf32.f32 "
        "{%0,%1,%2,%3}, {%4,%5,%6,%7}, {%8,%9}, {%0,%1,%2,%3};"
        : "+f"(c[0]), "+f"(c[1]), "+f"(c[2]), "+f"(c[3])
        : "r"(a[0]), "r"(a[1]), "r"(a[2]), "r"(a[3]), "r"(b[0]), "r"(b[1]));
}

// 32x32x128 warp GEMM with INLINE cvt (+optional per-k scale). Used by K1.
// AT: element (m,k) at A[k*sa+m].
template<bool AT, bool SC>
__device__ __forceinline__ void gemm32c(const float* __restrict__ A, int sa,
                                        const float* __restrict__ B, int sb,
                                        const float* __restrict__ kd,
                                        float acc[2][4][4], int rb, int cb, int lane){
    const int lr = lane >> 2, lc = lane & 3;
#pragma unroll
    for (int ks = 0; ks < 16; ks++){
        const int kc = ks * 8 + lc;
        uint32_t a[2][4];
#pragma unroll
        for (int mt = 0; mt < 2; mt++){
            const int m = rb + mt * 16 + lr;
            float a0, a1, a2, a3;
            if (AT){
                a0 = A[kc * sa + m];       a1 = A[kc * sa + m + 8];
                a2 = A[(kc + 4) * sa + m]; a3 = A[(kc + 4) * sa + m + 8];
            } else {
                a0 = A[m * sa + kc];       a1 = A[(m + 8) * sa + kc];
                a2 = A[m * sa + kc + 4];   a3 = A[(m + 8) * sa + kc + 4];
            }
            if (SC){
                float s0 = kd[kc], s4 = kd[kc + 4];
                a0 *= s0; a1 *= s0; a2 *= s4; a3 *= s4;
            }
            a[mt][0] = f2tf(a0); a[mt][1] = f2tf(a1);
            a[mt][2] = f2tf(a2); a[mt][3] = f2tf(a3);
        }
#pragma unroll
        for (int nt = 0; nt < 4; nt++){
            const int n = cb + nt * 8 + lr;
            uint32_t b[2] = { f2tf(B[kc * sb + n]), f2tf(B[(kc + 4) * sb + n]) };
            mma8(acc[0][nt], a[0], b);
            mma8(acc[1][nt], a[1], b);
        }
    }
}

// 32x32x128 warp GEMM on PRE-CONVERTED tf32 tiles (raw loads). Used by K3.
// BT: element (k,n) at B[n*sb+k].
template<bool BT>
__device__ __forceinline__ void gemm32r(const uint32_t* __restrict__ A, int sa,
                                        const uint32_t* __restrict__ B, int sb,
                                        float acc[2][4][4], int rb, int cb, int lane){
    const int lr = lane >> 2, lc = lane & 3;
#pragma unroll
    for (int ks = 0; ks < 16; ks++){
        const int kc = ks * 8 + lc;
        uint32_t a[2][4];
#pragma unroll
        for (int mt = 0; mt < 2; mt++){
            const int m = rb + mt * 16 + lr;
            a[mt][0] = A[m * sa + kc];       a[mt][1] = A[(m + 8) * sa + kc];
            a[mt][2] = A[m * sa + kc + 4];   a[mt][3] = A[(m + 8) * sa + kc + 4];
        }
#pragma unroll
        for (int nt = 0; nt < 4; nt++){
            const int n = cb + nt * 8 + lr;
            uint32_t b[2];
            if (BT){ b[0] = B[n * sb + kc];  b[1] = B[n * sb + kc + 4]; }
            else   { b[0] = B[kc * sb + n];  b[1] = B[(kc + 4) * sb + n]; }
            mma8(acc[0][nt], a[0], b);
            mma8(acc[1][nt], a[1], b);
        }
    }
}

__device__ __forceinline__ void fill_tile(uint32_t sdst, const float* gsrc, int gstride_f,
                                          int rowbytes, int sstride_b, int rows,
                                          int tid, int nthr){
    const int cpr = rowbytes >> 4;
    const int total = rows * cpr;
    for (int i = tid; i < total; i += nthr){
        int r = i / cpr, c = i - r * cpr;
        cpa16(sdst + r * sstride_b + c * 16, (const char*)gsrc + (size_t)r * gstride_f * 4 + c * 16);
    }
}

// In-place fp32 -> tf32 (rna) conversion of a tile; f4pr = float4s per row.
__device__ __forceinline__ void cvt_tile(float* t, int stride, int rows, int f4pr,
                                         int tid, int nthr){
    const int total = rows * f4pr;
    for (int i = tid; i < total; i += nthr){
        int r = i / f4pr, c4 = (i - r * f4pr) * 4;
        float4* p = (float4*)(t + r * stride + c4);
        float4 v = *p;
        *(uint4*)p = make_uint4(f2tf(v.x), f2tf(v.y), f2tf(v.z), f2tf(v.w));
    }
}

// ---------------- K1: C_j = (k * k_decay)^T @ v  (half of d-rows per CTA) ----------------
__global__ void __launch_bounds__(256) k_chunkKV(const float* __restrict__ k,
                                                 const float* __restrict__ v,
                                                 const float* __restrict__ s){
    extern __shared__ float sm[];
    float* kd  = sm;
    float* ksm = sm + 128;
    float* vsm = ksm + 128 * SDK;
    const int tid = threadIdx.x, w = tid >> 5, lane = tid & 31;
    const int g = blockIdx.x >> 1, dh = blockIdx.x & 1, bh = g >> 5;
    const float sh = __ldg(&s[bh & 15]);
    const size_t base = ((size_t)bh * 4096 + (size_t)(g & 31) * 128) * 128;
    const uint32_t sb = s2u(sm);

    fill_tile(sb + 128 * 4, k + base + dh * 64, 128, 256, SDK * 4, 128, tid, 256);
    fill_tile(sb + (128 + 128 * SDK) * 4, v + base, 128, 512, SD * 4, 128, tid, 256);
    CP_COMMIT();
    if (tid < 128) kd[tid] = __expf(-sh * (float)(128 - tid));
    CP_WAIT0();
    __syncthreads();

    const int rb = (w & 1) * 32, cb = (w >> 1) * 32;
    float acc[2][4][4] = {};
    gemm32c<true, true>(ksm, SDK, vsm, SD, kd, acc, rb, cb, lane);

    float* C = g_C + (size_t)g * 16384 + (size_t)dh * 64 * 128;
    const int lr = lane >> 2, lc2 = (lane & 3) * 2;
#pragma unroll
    for (int mt = 0; mt < 2; mt++){
        const int r = rb + mt * 16 + lr;
#pragma unroll
        for (int nt = 0; nt < 4; nt++){
            const int c = cb + nt * 8 + lc2;
            *(float2*)(C + (size_t)r * 128 + c)       = make_float2(acc[mt][nt][0], acc[mt][nt][1]);
            *(float2*)(C + (size_t)(r + 8) * 128 + c) = make_float2(acc[mt][nt][2], acc[mt][nt][3]);
        }
    }
}

// ---------------- K2: exclusive decayed prefix scan, g_C -> g_S (tf32 out) ----------------
__global__ void __launch_bounds__(256) k_scan(const float* __restrict__ s){
    const int bh = blockIdx.y;
    const int e4 = blockIdx.x * 256 + threadIdx.x;
    const float lamB = __expf(-__ldg(&s[bh & 15]) * 128.0f);
    const float4* __restrict__ src = (const float4*)(g_C + (size_t)bh * 32 * 16384) + e4;
    uint4* __restrict__ dst        = (uint4*)(g_S + (size_t)bh * 32 * 16384) + e4;

    float4 val = make_float4(0.f, 0.f, 0.f, 0.f);
    float4 c = src[0];
#pragma unroll
    for (int j = 0; j < 32; j++){
        float4 cn = (j < 31) ? src[(j + 1) * 4096] : make_float4(0.f, 0.f, 0.f, 0.f);
        dst[j * 4096] = make_uint4(f2tf(val.x), f2tf(val.y), f2tf(val.z), f2tf(val.w));
        val.x = lamB * val.x + c.x;
        val.y = lamB * val.y + c.y;
        val.z = lamB * val.z + c.z;
        val.w = lamB * val.w + c.w;
        c = cn;
    }
}

// ---------------- K3: output (GEMM2 first; K and V fills overlapped) ----------------
__global__ void __launch_bounds__(512) k_output(const float* __restrict__ q,
                                                const float* __restrict__ k,
                                                const float* __restrict__ v,
                                                const float* __restrict__ s,
                                                float* __restrict__ o){
    extern __shared__ float sm[];
    float* dec  = sm;
    float* Qs   = sm + 128;              // Q (tf32 after cvt)
    float* buf1 = Qs + 128 * SD;         // K, later scores
    float* buf2 = buf1 + 128 * SD;       // S (tf32 from scan), later V
    const int tid = threadIdx.x, w = tid >> 5, lane = tid & 31;
    const int g = blockIdx.x, bh = g >> 5;
    const float sh = __ldg(&s[bh & 15]);
    const size_t base = ((size_t)bh * 4096 + (size_t)(g & 31) * 128) * 128;
    const uint32_t sb = s2u(sm);
    const uint32_t oQ = sb + 128 * 4, o1 = oQ + 128 * SD * 4, o2 = o1 + 128 * SD * 4;

    fill_tile(oQ, q + base, 128, 512, SD * 4, 128, tid, 512);
    fill_tile(o2, g_S + (size_t)g * 16384, 128, 512, SD * 4, 128, tid, 512);
    CP_COMMIT();                                           // group A: Q + S
    fill_tile(o1, k + base, 128, 512, SD * 4, 128, tid, 512);
    CP_COMMIT();                                           // group B: K (lands under GEMM2)
    if (tid < 128) dec[tid] = __expf(-sh * (float)tid);
    CP_WAIT1();                                            // Q + S ready
    __syncthreads();

    cvt_tile(Qs, SD, 128, 32, tid, 512);                   // Q -> tf32 (S already tf32)
    __syncthreads();

    const int rb = (w >> 2) * 32, cb = (w & 3) * 32;
    const int lr = lane >> 2, lc2 = (lane & 3) * 2;

    float acc2[2][4][4] = {};   // inter = Q @ S  (first: frees buf2 early)
    gemm32r<false>((const uint32_t*)Qs, SD, (const uint32_t*)buf2, SD, acc2, rb, cb, lane);

    CP_WAIT0();                 // K in
    __syncthreads();            // all warps done reading buf2 (S)

    // V fill into buf2: overlaps cvt-K + GEMM1 + epilogue
    fill_tile(o2, v + base, 128, 512, SD * 4, 128, tid, 512);
    CP_COMMIT();

    cvt_tile(buf1, SD, 128, 32, tid, 512);                 // K -> tf32
    __syncthreads();

    float acc1[2][4][4] = {};   // scores = Q @ K^T
    gemm32r<true>((const uint32_t*)Qs, SD, (const uint32_t*)buf1, SD, acc1, rb, cb, lane);
    __syncthreads();            // all warps done reading buf1 (K)

    // epilogue: mask+decay scores -> buf1 as tf32; pre-scale inter by q_decay
    uint32_t* sc = (uint32_t*)buf1;
#pragma unroll
    for (int mt = 0; mt < 2; mt++){
        const int r = rb + mt * 16 + lr;
        const float e0 = dec[r], e8 = dec[r + 8];
#pragma unroll
        for (int nt = 0; nt < 4; nt++){
            const int c = cb + nt * 8 + lc2;
            uint32_t v00 = f2tf((r     >= c    ) ? acc1[mt][nt][0] * dec[r - c]     : 0.0f);
            uint32_t v01 = f2tf((r     >= c + 1) ? acc1[mt][nt][1] * dec[r - c - 1] : 0.0f);
            uint32_t v10 = f2tf((r + 8 >= c    ) ? acc1[mt][nt][2] * dec[r + 8 - c] : 0.0f);
            uint32_t v11 = f2tf((r + 8 >= c + 1) ? acc1[mt][nt][3] * dec[r + 7 - c] : 0.0f);
            *(uint2*)(sc + r * SD + c)       = make_uint2(v00, v01);
            *(uint2*)(sc + (r + 8) * SD + c) = make_uint2(v10, v11);
            acc2[mt][nt][0] *= e0; acc2[mt][nt][1] *= e0;
            acc2[mt][nt][2] *= e8; acc2[mt][nt][3] *= e8;
        }
    }
    CP_WAIT0();
    __syncthreads();            // V in, scores visible

    cvt_tile(buf2, SD, 128, 32, tid, 512);                 // V -> tf32
    __syncthreads();

    // out = qdec*(Q@S) + scores @ V
    gemm32r<false>((const uint32_t*)buf1, SD, (const uint32_t*)buf2, SD, acc2, rb, cb, lane);

#pragma unroll
    for (int mt = 0; mt < 2; mt++){
        const int r = rb + mt * 16 + lr;
#pragma unroll
        for (int nt = 0; nt < 4; nt++){
            const int c = cb + nt * 8 + lc2;
            *(float2*)(o + base + (size_t)r * 128 + c)       = make_float2(acc2[mt][nt][0], acc2[mt][nt][1]);
            *(float2*)(o + base + (size_t)(r + 8) * 128 + c) = make_float2(acc2[mt][nt][2], acc2[mt][nt][3]);
        }
    }
}

extern "C" void kernel_launch(void* const* d_in, const int* in_sizes, int n_in,
                              void* d_out, int out_size) {
    const float* q = (const float*)d_in[0];
    const float* k = (const float*)d_in[1];
    const float* v = (const float*)d_in[2];
    const float* s = (const float*)d_in[3];
    float* o = (float*)d_out;

    const int sm1 = (128 + 128 * SDK + 128 * SD) * 4;       // 107,008 B
    const int sm3 = (128 + 3 * 128 * SD) * 4;               // 209,408 B
    cudaFuncSetAttribute(k_chunkKV, cudaFuncAttributeMaxDynamicSharedMemorySize, sm1);
    cudaFuncSetAttribute(k_output,  cudaFuncAttributeMaxDynamicSharedMemorySize, sm3);

    k_chunkKV<<<2048, 256, sm1>>>(k, v, s);
    k_scan<<<dim3(16, 32), 256>>>(s);
    k_output<<<1024, 512, sm3>>>(q, k, v, s, o);
}

// round 10
// speedup vs baseline: 5.0250x; 1.0280x over previous
#include <cuda_runtime.h>
#include <cstdint>

// Lightning attention, chunked-parallel, mma.sync tf32 (row.col), cp.async fills.
//   K1: C quadrants = (k*k_decay)^T @ v  (4096 CTAs, 64x64x128, 3 CTAs/SM)
//   K2: exclusive decayed prefix scan g_C -> g_S (pure streams, float4; S stored tf32)
//   K3: O = qdec*(Q@S) + (mask(Q K^T))@V  (all cvt inline, zero cvt passes)

#define SD  136   // smem row stride (words) for 128-col tiles (136%32==8, conflict-free)
#define SDH 72    // smem row stride for 64-col half tiles     (72%32==8)

__device__ float g_C[1024u * 16384u];   // 64 MB: chunk KV products
__device__ float g_S[1024u * 16384u];   // 64 MB: scanned exclusive states (tf32 bits)

__device__ __forceinline__ uint32_t f2tf(float x){
    uint32_t r; asm("cvt.rna.tf32.f32 %0, %1;" : "=r"(r) : "f"(x)); return r;
}
__device__ __forceinline__ uint32_t s2u(const void* p){
    uint32_t a;
    asm("{ .reg .u64 t; cvta.to.shared.u64 t, %1; cvt.u32.u64 %0, t; }" : "=r"(a) : "l"(p));
    return a;
}
__device__ __forceinline__ void cpa16(uint32_t dst, const void* src){
    asm volatile("cp.async.cg.shared.global [%0], [%1], 16;" :: "r"(dst), "l"(src));
}
#define CP_COMMIT() asm volatile("cp.async.commit_group;" ::: "memory")
#define CP_WAIT0()  asm volatile("cp.async.wait_group 0;" ::: "memory")
#define CP_WAIT1()  asm volatile("cp.async.wait_group 1;" ::: "memory")

__device__ __forceinline__ void mma8(float* c, const uint32_t* a, const uint32_t* b){
    asm volatile(
        "mma.sync.aligned.m16n8k8.row.col.f32.tf32.tf32.f32 "
        "{%0,%1,%2,%3}, {%4,%5,%6,%7}, {%8,%9}, {%0,%1,%2,%3};"
        : "+f"(c[0]), "+f"(c[1]), "+f"(c[2]), "+f"(c[3])
        : "r"(a[0]), "r"(a[1]), "r"(a[2]), "r"(a[3]), "r"(b[0]), "r"(b[1]));
}

// K1 warp GEMM: 32(m) x 16(n) x 128. A transposed-indexed + per-k scale + cvt; B natural + cvt.
__device__ __forceinline__ void gemm_k1(const float* __restrict__ A, int sa,
                                        const float* __restrict__ B, int sb,
                                        const float* __restrict__ kd,
                                        float acc[2][2][4], int rb, int cb, int lane){
    const int lr = lane >> 2, lc = lane & 3;
#pragma unroll
    for (int ks = 0; ks < 16; ks++){
        const int kc = ks * 8 + lc;
        const float s0 = kd[kc], s4 = kd[kc + 4];
        uint32_t a[2][4];
#pragma unroll
        for (int mt = 0; mt < 2; mt++){
            const int m = rb + mt * 16 + lr;
            a[mt][0] = f2tf(A[kc * sa + m] * s0);
            a[mt][1] = f2tf(A[kc * sa + m + 8] * s0);
            a[mt][2] = f2tf(A[(kc + 4) * sa + m] * s4);
            a[mt][3] = f2tf(A[(kc + 4) * sa + m + 8] * s4);
        }
#pragma unroll
        for (int nt = 0; nt < 2; nt++){
            const int n = cb + nt * 8 + lr;
            uint32_t b[2] = { f2tf(B[kc * sb + n]), f2tf(B[(kc + 4) * sb + n]) };
            mma8(acc[0][nt], a[0], b);
            mma8(acc[1][nt], a[1], b);
        }
    }
}

// K3 warp GEMM: 32x32x128. CVTA/CVTB: operand is fp32, convert inline; else raw tf32 bits.
// BT: element (k,n) at B[n*sb+k].
template<bool CVTA, bool BT, bool CVTB>
__device__ __forceinline__ void gemm_k3(const float* __restrict__ A, int sa,
                                        const float* __restrict__ B, int sb,
                                        float acc[2][4][4], int rb, int cb, int lane){
    const int lr = lane >> 2, lc = lane & 3;
#pragma unroll
    for (int ks = 0; ks < 16; ks++){
        const int kc = ks * 8 + lc;
        uint32_t a[2][4];
#pragma unroll
        for (int mt = 0; mt < 2; mt++){
            const int m = rb + mt * 16 + lr;
            float a0 = A[m * sa + kc],     a1 = A[(m + 8) * sa + kc];
            float a2 = A[m * sa + kc + 4], a3 = A[(m + 8) * sa + kc + 4];
            if (CVTA){
                a[mt][0] = f2tf(a0); a[mt][1] = f2tf(a1);
                a[mt][2] = f2tf(a2); a[mt][3] = f2tf(a3);
            } else {
                a[mt][0] = __float_as_uint(a0); a[mt][1] = __float_as_uint(a1);
                a[mt][2] = __float_as_uint(a2); a[mt][3] = __float_as_uint(a3);
            }
        }
#pragma unroll
        for (int nt = 0; nt < 4; nt++){
            const int n = cb + nt * 8 + lr;
            float b0v, b1v;
            if (BT){ b0v = B[n * sb + kc];  b1v = B[n * sb + kc + 4]; }
            else   { b0v = B[kc * sb + n];  b1v = B[(kc + 4) * sb + n]; }
            uint32_t b[2];
            if (CVTB){ b[0] = f2tf(b0v);             b[1] = f2tf(b1v); }
            else     { b[0] = __float_as_uint(b0v);  b[1] = __float_as_uint(b1v); }
            mma8(acc[0][nt], a[0], b);
            mma8(acc[1][nt], a[1], b);
        }
    }
}

__device__ __forceinline__ void fill_tile(uint32_t sdst, const float* gsrc, int gstride_f,
                                          int rowbytes, int sstride_b, int rows,
                                          int tid, int nthr){
    const int cpr = rowbytes >> 4;
    const int total = rows * cpr;
    for (int i = tid; i < total; i += nthr){
        int r = i / cpr, c = i - r * cpr;
        cpa16(sdst + r * sstride_b + c * 16, (const char*)gsrc + (size_t)r * gstride_f * 4 + c * 16);
    }
}

// ---------------- K1: C quadrant = (k_half * k_decay)^T @ v_half ----------------
__global__ void __launch_bounds__(256) k_chunkKV(const float* __restrict__ k,
                                                 const float* __restrict__ v,
                                                 const float* __restrict__ s){
    extern __shared__ float sm[];
    float* kd  = sm;                    // 128 floats
    float* ksm = sm + 128;              // [tau][d-half], SDH stride
    float* vsm = ksm + 128 * SDH;       // [tau][e-half], SDH stride
    const int tid = threadIdx.x, w = tid >> 5, lane = tid & 31;
    const int g = blockIdx.x >> 2, quad = blockIdx.x & 3;
    const int dh = quad >> 1, eh = quad & 1, bh = g >> 5;
    const float sh = __ldg(&s[bh & 15]);
    const size_t base = ((size_t)bh * 4096 + (size_t)(g & 31) * 128) * 128;
    const uint32_t sb = s2u(sm);

    fill_tile(sb + 128 * 4, k + base + dh * 64, 128, 256, SDH * 4, 128, tid, 256);
    fill_tile(sb + (128 + 128 * SDH) * 4, v + base + eh * 64, 128, 256, SDH * 4, 128, tid, 256);
    CP_COMMIT();
    if (tid < 128) kd[tid] = __expf(-sh * (float)(128 - tid));
    CP_WAIT0();
    __syncthreads();

    const int rb = (w & 1) * 32, cb = (w >> 1) * 16;
    float acc[2][2][4] = {};
    gemm_k1(ksm, SDH, vsm, SDH, kd, acc, rb, cb, lane);

    float* C = g_C + (size_t)g * 16384 + (size_t)dh * 64 * 128 + eh * 64;
    const int lr = lane >> 2, lc2 = (lane & 3) * 2;
#pragma unroll
    for (int mt = 0; mt < 2; mt++){
        const int r = rb + mt * 16 + lr;
#pragma unroll
        for (int nt = 0; nt < 2; nt++){
            const int c = cb + nt * 8 + lc2;
            *(float2*)(C + (size_t)r * 128 + c)       = make_float2(acc[mt][nt][0], acc[mt][nt][1]);
            *(float2*)(C + (size_t)(r + 8) * 128 + c) = make_float2(acc[mt][nt][2], acc[mt][nt][3]);
        }
    }
}

// ---------------- K2: exclusive decayed prefix scan, g_C -> g_S (tf32 out) ----------------
__global__ void __launch_bounds__(256) k_scan(const float* __restrict__ s){
    const int bh = blockIdx.y;
    const int e4 = blockIdx.x * 256 + threadIdx.x;
    const float lamB = __expf(-__ldg(&s[bh & 15]) * 128.0f);
    const float4* __restrict__ src = (const float4*)(g_C + (size_t)bh * 32 * 16384) + e4;
    uint4* __restrict__ dst        = (uint4*)(g_S + (size_t)bh * 32 * 16384) + e4;

    float4 val = make_float4(0.f, 0.f, 0.f, 0.f);
    float4 c = src[0];
#pragma unroll
    for (int j = 0; j < 32; j++){
        float4 cn = (j < 31) ? src[(j + 1) * 4096] : make_float4(0.f, 0.f, 0.f, 0.f);
        dst[j * 4096] = make_uint4(f2tf(val.x), f2tf(val.y), f2tf(val.z), f2tf(val.w));
        val.x = lamB * val.x + c.x;
        val.y = lamB * val.y + c.y;
        val.z = lamB * val.z + c.z;
        val.w = lamB * val.w + c.w;
        c = cn;
    }
}

// ---------------- K3: output (inline cvt everywhere, no cvt passes) ----------------
__global__ void __launch_bounds__(512) k_output(const float* __restrict__ q,
                                                const float* __restrict__ k,
                                                const float* __restrict__ v,
                                                const float* __restrict__ s,
                                                float* __restrict__ o){
    extern __shared__ float sm[];
    float* dec  = sm;
    float* Qs   = sm + 128;              // Q (fp32, cvt inline)
    float* buf1 = Qs + 128 * SD;         // K (fp32), later scores (tf32 bits)
    float* buf2 = buf1 + 128 * SD;       // S (tf32 bits from scan), later V (fp32)
    const int tid = threadIdx.x, w = tid >> 5, lane = tid & 31;
    const int g = blockIdx.x, bh = g >> 5;
    const float sh = __ldg(&s[bh & 15]);
    const size_t base = ((size_t)bh * 4096 + (size_t)(g & 31) * 128) * 128;
    const uint32_t sb = s2u(sm);
    const uint32_t oQ = sb + 128 * 4, o1 = oQ + 128 * SD * 4, o2 = o1 + 128 * SD * 4;

    fill_tile(oQ, q + base, 128, 512, SD * 4, 128, tid, 512);
    fill_tile(o2, g_S + (size_t)g * 16384, 128, 512, SD * 4, 128, tid, 512);
    CP_COMMIT();                                           // group A: Q + S
    fill_tile(o1, k + base, 128, 512, SD * 4, 128, tid, 512);
    CP_COMMIT();                                           // group B: K
    if (tid < 128) dec[tid] = __expf(-sh * (float)tid);
    CP_WAIT1();                                            // Q + S ready
    __syncthreads();

    const int rb = (w >> 2) * 32, cb = (w & 3) * 32;
    const int lr = lane >> 2, lc2 = (lane & 3) * 2;

    float acc2[2][4][4] = {};   // inter = Q @ S  (A: cvt; B: raw tf32, natural)
    gemm_k3<true, false, false>(Qs, SD, buf2, SD, acc2, rb, cb, lane);

    CP_WAIT0();                 // K in
    __syncthreads();            // all warps done reading buf2 (S)

    // V fill into buf2: overlaps GEMM1 + epilogue
    fill_tile(o2, v + base, 128, 512, SD * 4, 128, tid, 512);
    CP_COMMIT();

    float acc1[2][4][4] = {};   // scores = Q @ K^T  (A: cvt; B: cvt, transposed-indexed)
    gemm_k3<true, true, true>(Qs, SD, buf1, SD, acc1, rb, cb, lane);
    __syncthreads();            // all warps done reading buf1 (K)

    // epilogue: mask+decay scores -> buf1 as tf32 bits; pre-scale inter by q_decay
    uint32_t* sc = (uint32_t*)buf1;
#pragma unroll
    for (int mt = 0; mt < 2; mt++){
        const int r = rb + mt * 16 + lr;
        const float e0 = dec[r], e8 = dec[r + 8];
#pragma unroll
        for (int nt = 0; nt < 4; nt++){
            const int c = cb + nt * 8 + lc2;
            uint32_t v00 = f2tf((r     >= c    ) ? acc1[mt][nt][0] * dec[r - c]     : 0.0f);
            uint32_t v01 = f2tf((r     >= c + 1) ? acc1[mt][nt][1] * dec[r - c - 1] : 0.0f);
            uint32_t v10 = f2tf((r + 8 >= c    ) ? acc1[mt][nt][2] * dec[r + 8 - c] : 0.0f);
            uint32_t v11 = f2tf((r + 8 >= c + 1) ? acc1[mt][nt][3] * dec[r + 7 - c] : 0.0f);
            *(uint2*)(sc + r * SD + c)       = make_uint2(v00, v01);
            *(uint2*)(sc + (r + 8) * SD + c) = make_uint2(v10, v11);
            acc2[mt][nt][0] *= e0; acc2[mt][nt][1] *= e0;
            acc2[mt][nt][2] *= e8; acc2[mt][nt][3] *= e8;
        }
    }
    CP_WAIT0();
    __syncthreads();            // V in, scores visible

    // out = qdec*(Q@S) + scores @ V  (A: raw tf32 scores; B: cvt V, natural)
    gemm_k3<false, false, true>(buf1, SD, buf2, SD, acc2, rb, cb, lane);

#pragma unroll
    for (int mt = 0; mt < 2; mt++){
        const int r = rb + mt * 16 + lr;
#pragma unroll
        for (int nt = 0; nt < 4; nt++){
            const int c = cb + nt * 8 + lc2;
            *(float2*)(o + base + (size_t)r * 128 + c)       = make_float2(acc2[mt][nt][0], acc2[mt][nt][1]);
            *(float2*)(o + base + (size_t)(r + 8) * 128 + c) = make_float2(acc2[mt][nt][2], acc2[mt][nt][3]);
        }
    }
}

extern "C" void kernel_launch(void* const* d_in, const int* in_sizes, int n_in,
                              void* d_out, int out_size) {
    const float* q = (const float*)d_in[0];
    const float* k = (const float*)d_in[1];
    const float* v = (const float*)d_in[2];
    const float* s = (const float*)d_in[3];
    float* o = (float*)d_out;

    const int sm1 = (128 + 2 * 128 * SDH) * 4;              // 74,240 B  (3 CTAs/SM)
    const int sm3 = (128 + 3 * 128 * SD) * 4;               // 209,408 B
    cudaFuncSetAttribute(k_chunkKV, cudaFuncAttributeMaxDynamicSharedMemorySize, sm1);
    cudaFuncSetAttribute(k_output,  cudaFuncAttributeMaxDynamicSharedMemorySize, sm3);

    k_chunkKV<<<4096, 256, sm1>>>(k, v, s);
    k_scan<<<dim3(16, 32), 256>>>(s);
    k_output<<<1024, 512, sm3>>>(q, k, v, s, o);
}

// round 11
// speedup vs baseline: 5.2010x; 1.0350x over previous
#include <cuda_runtime.h>
#include <cstdint>

// Lightning attention, chunked-parallel, mma.sync tf32 (row.col), cp.async fills.
//   K1: C_j = (k*k_decay)^T @ v   (2048 CTAs, 64x128x128, inline cvt+scale, 2 CTAs/SM)
//   K2: exclusive decayed prefix scan g_C -> g_S (pure streams, float4; S stored tf32)
//   K3: O = qdec*(Q@S) + (mask(Q K^T))@V  (all cvt inline, zero cvt passes)

#define SD  136   // smem row stride (words) for 128-col tiles (136%32==8, conflict-free)
#define SDK 72    // smem row stride for K1's 64-col k tile    (72%32==8)

__device__ float g_C[1024u * 16384u];   // 64 MB: chunk KV products
__device__ float g_S[1024u * 16384u];   // 64 MB: scanned exclusive states (tf32 bits)

__device__ __forceinline__ uint32_t f2tf(float x){
    uint32_t r; asm("cvt.rna.tf32.f32 %0, %1;" : "=r"(r) : "f"(x)); return r;
}
__device__ __forceinline__ uint32_t s2u(const void* p){
    uint32_t a;
    asm("{ .reg .u64 t; cvta.to.shared.u64 t, %1; cvt.u32.u64 %0, t; }" : "=r"(a) : "l"(p));
    return a;
}
__device__ __forceinline__ void cpa16(uint32_t dst, const void* src){
    asm volatile("cp.async.cg.shared.global [%0], [%1], 16;" :: "r"(dst), "l"(src));
}
#define CP_COMMIT() asm volatile("cp.async.commit_group;" ::: "memory")
#define CP_WAIT0()  asm volatile("cp.async.wait_group 0;" ::: "memory")
#define CP_WAIT1()  asm volatile("cp.async.wait_group 1;" ::: "memory")

__device__ __forceinline__ void mma8(float* c, const uint32_t* a, const uint32_t* b){
    asm volatile(
        "mma.sync.aligned.m16n8k8.row.col.f32.tf32.tf32.f32 "
        "{%0,%1,%2,%3}, {%4,%5,%6,%7}, {%8,%9}, {%0,%1,%2,%3};"
        : "+f"(c[0]), "+f"(c[1]), "+f"(c[2]), "+f"(c[3])
        : "r"(a[0]), "r"(a[1]), "r"(a[2]), "r"(a[3]), "r"(b[0]), "r"(b[1]));
}

// K1 warp GEMM: 32(m) x 32(n) x 128. A transposed-indexed + per-k scale + cvt; B natural + cvt.
__device__ __forceinline__ void gemm_k1(const float* __restrict__ A, int sa,
                                        const float* __restrict__ B, int sb,
                                        const float* __restrict__ kd,
                                        float acc[2][4][4], int rb, int cb, int lane){
    const int lr = lane >> 2, lc = lane & 3;
#pragma unroll
    for (int ks = 0; ks < 16; ks++){
        const int kc = ks * 8 + lc;
        const float s0 = kd[kc], s4 = kd[kc + 4];
        uint32_t a[2][4];
#pragma unroll
        for (int mt = 0; mt < 2; mt++){
            const int m = rb + mt * 16 + lr;
            a[mt][0] = f2tf(A[kc * sa + m] * s0);
            a[mt][1] = f2tf(A[kc * sa + m + 8] * s0);
            a[mt][2] = f2tf(A[(kc + 4) * sa + m] * s4);
            a[mt][3] = f2tf(A[(kc + 4) * sa + m + 8] * s4);
        }
#pragma unroll
        for (int nt = 0; nt < 4; nt++){
            const int n = cb + nt * 8 + lr;
            uint32_t b[2] = { f2tf(B[kc * sb + n]), f2tf(B[(kc + 4) * sb + n]) };
            mma8(acc[0][nt], a[0], b);
            mma8(acc[1][nt], a[1], b);
        }
    }
}

// K3 warp GEMM: 32x32x128. CVTA/CVTB: operand is fp32, convert inline; else raw tf32 bits.
// BT: element (k,n) at B[n*sb+k].
template<bool CVTA, bool BT, bool CVTB>
__device__ __forceinline__ void gemm_k3(const float* __restrict__ A, int sa,
                                        const float* __restrict__ B, int sb,
                                        float acc[2][4][4], int rb, int cb, int lane){
    const int lr = lane >> 2, lc = lane & 3;
#pragma unroll
    for (int ks = 0; ks < 16; ks++){
        const int kc = ks * 8 + lc;
        uint32_t a[2][4];
#pragma unroll
        for (int mt = 0; mt < 2; mt++){
            const int m = rb + mt * 16 + lr;
            float a0 = A[m * sa + kc],     a1 = A[(m + 8) * sa + kc];
            float a2 = A[m * sa + kc + 4], a3 = A[(m + 8) * sa + kc + 4];
            if (CVTA){
                a[mt][0] = f2tf(a0); a[mt][1] = f2tf(a1);
                a[mt][2] = f2tf(a2); a[mt][3] = f2tf(a3);
            } else {
                a[mt][0] = __float_as_uint(a0); a[mt][1] = __float_as_uint(a1);
                a[mt][2] = __float_as_uint(a2); a[mt][3] = __float_as_uint(a3);
            }
        }
#pragma unroll
        for (int nt = 0; nt < 4; nt++){
            const int n = cb + nt * 8 + lr;
            float b0v, b1v;
            if (BT){ b0v = B[n * sb + kc];  b1v = B[n * sb + kc + 4]; }
            else   { b0v = B[kc * sb + n];  b1v = B[(kc + 4) * sb + n]; }
            uint32_t b[2];
            if (CVTB){ b[0] = f2tf(b0v);             b[1] = f2tf(b1v); }
            else     { b[0] = __float_as_uint(b0v);  b[1] = __float_as_uint(b1v); }
            mma8(acc[0][nt], a[0], b);
            mma8(acc[1][nt], a[1], b);
        }
    }
}

__device__ __forceinline__ void fill_tile(uint32_t sdst, const float* gsrc, int gstride_f,
                                          int rowbytes, int sstride_b, int rows,
                                          int tid, int nthr){
    const int cpr = rowbytes >> 4;
    const int total = rows * cpr;
    for (int i = tid; i < total; i += nthr){
        int r = i / cpr, c = i - r * cpr;
        cpa16(sdst + r * sstride_b + c * 16, (const char*)gsrc + (size_t)r * gstride_f * 4 + c * 16);
    }
}

// ---------------- K1: C_j = (k * k_decay)^T @ v  (half of d-rows per CTA) ----------------
__global__ void __launch_bounds__(256) k_chunkKV(const float* __restrict__ k,
                                                 const float* __restrict__ v,
                                                 const float* __restrict__ s){
    extern __shared__ float sm[];
    float* kd  = sm;                    // 128 floats
    float* ksm = sm + 128;              // [tau][d-half], SDK stride
    float* vsm = ksm + 128 * SDK;       // [tau][e], SD stride
    const int tid = threadIdx.x, w = tid >> 5, lane = tid & 31;
    const int g = blockIdx.x >> 1, dh = blockIdx.x & 1, bh = g >> 5;
    const float sh = __ldg(&s[bh & 15]);
    const size_t base = ((size_t)bh * 4096 + (size_t)(g & 31) * 128) * 128;
    const uint32_t sb = s2u(sm);

    fill_tile(sb + 128 * 4, k + base + dh * 64, 128, 256, SDK * 4, 128, tid, 256);
    fill_tile(sb + (128 + 128 * SDK) * 4, v + base, 128, 512, SD * 4, 128, tid, 256);
    CP_COMMIT();
    if (tid < 128) kd[tid] = __expf(-sh * (float)(128 - tid));
    CP_WAIT0();
    __syncthreads();

    const int rb = (w & 1) * 32, cb = (w >> 1) * 32;
    float acc[2][4][4] = {};
    gemm_k1(ksm, SDK, vsm, SD, kd, acc, rb, cb, lane);

    float* C = g_C + (size_t)g * 16384 + (size_t)dh * 64 * 128;
    const int lr = lane >> 2, lc2 = (lane & 3) * 2;
#pragma unroll
    for (int mt = 0; mt < 2; mt++){
        const int r = rb + mt * 16 + lr;
#pragma unroll
        for (int nt = 0; nt < 4; nt++){
            const int c = cb + nt * 8 + lc2;
            *(float2*)(C + (size_t)r * 128 + c)       = make_float2(acc[mt][nt][0], acc[mt][nt][1]);
            *(float2*)(C + (size_t)(r + 8) * 128 + c) = make_float2(acc[mt][nt][2], acc[mt][nt][3]);
        }
    }
}

// ---------------- K2: exclusive decayed prefix scan, g_C -> g_S (tf32 out) ----------------
__global__ void __launch_bounds__(256) k_scan(const float* __restrict__ s){
    const int bh = blockIdx.y;
    const int e4 = blockIdx.x * 256 + threadIdx.x;
    const float lamB = __expf(-__ldg(&s[bh & 15]) * 128.0f);
    const float4* __restrict__ src = (const float4*)(g_C + (size_t)bh * 32 * 16384) + e4;
    uint4* __restrict__ dst        = (uint4*)(g_S + (size_t)bh * 32 * 16384) + e4;

    float4 val = make_float4(0.f, 0.f, 0.f, 0.f);
    float4 c = src[0];
#pragma unroll
    for (int j = 0; j < 32; j++){
        float4 cn = (j < 31) ? src[(j + 1) * 4096] : make_float4(0.f, 0.f, 0.f, 0.f);
        dst[j * 4096] = make_uint4(f2tf(val.x), f2tf(val.y), f2tf(val.z), f2tf(val.w));
        val.x = lamB * val.x + c.x;
        val.y = lamB * val.y + c.y;
        val.z = lamB * val.z + c.z;
        val.w = lamB * val.w + c.w;
        c = cn;
    }
}

// ---------------- K3: output (inline cvt everywhere, no cvt passes) ----------------
__global__ void __launch_bounds__(512) k_output(const float* __restrict__ q,
                                                const float* __restrict__ k,
                                                const float* __restrict__ v,
                                                const float* __restrict__ s,
                                                float* __restrict__ o){
    extern __shared__ float sm[];
    float* dec  = sm;
    float* Qs   = sm + 128;              // Q (fp32, cvt inline)
    float* buf1 = Qs + 128 * SD;         // K (fp32), later scores (tf32 bits)
    float* buf2 = buf1 + 128 * SD;       // S (tf32 bits from scan), later V (fp32)
    const int tid = threadIdx.x, w = tid >> 5, lane = tid & 31;
    const int g = blockIdx.x, bh = g >> 5;
    const float sh = __ldg(&s[bh & 15]);
    const size_t base = ((size_t)bh * 4096 + (size_t)(g & 31) * 128) * 128;
    const uint32_t sb = s2u(sm);
    const uint32_t oQ = sb + 128 * 4, o1 = oQ + 128 * SD * 4, o2 = o1 + 128 * SD * 4;

    fill_tile(oQ, q + base, 128, 512, SD * 4, 128, tid, 512);
    fill_tile(o2, g_S + (size_t)g * 16384, 128, 512, SD * 4, 128, tid, 512);
    CP_COMMIT();                                           // group A: Q + S
    fill_tile(o1, k + base, 128, 512, SD * 4, 128, tid, 512);
    CP_COMMIT();                                           // group B: K
    if (tid < 128) dec[tid] = __expf(-sh * (float)tid);
    CP_WAIT1();                                            // Q + S ready
    __syncthreads();

    const int rb = (w >> 2) * 32, cb = (w & 3) * 32;
    const int lr = lane >> 2, lc2 = (lane & 3) * 2;

    float acc2[2][4][4] = {};   // inter = Q @ S  (A: cvt; B: raw tf32, natural)
    gemm_k3<true, false, false>(Qs, SD, buf2, SD, acc2, rb, cb, lane);

    CP_WAIT0();                 // K in
    __syncthreads();            // all warps done reading buf2 (S)

    // V fill into buf2: overlaps GEMM1 + epilogue
    fill_tile(o2, v + base, 128, 512, SD * 4, 128, tid, 512);
    CP_COMMIT();

    float acc1[2][4][4] = {};   // scores = Q @ K^T  (A: cvt; B: cvt, transposed-indexed)
    gemm_k3<true, true, true>(Qs, SD, buf1, SD, acc1, rb, cb, lane);
    __syncthreads();            // all warps done reading buf1 (K)

    // epilogue: mask+decay scores -> buf1 as tf32 bits; pre-scale inter by q_decay
    uint32_t* sc = (uint32_t*)buf1;
#pragma unroll
    for (int mt = 0; mt < 2; mt++){
        const int r = rb + mt * 16 + lr;
        const float e0 = dec[r], e8 = dec[r + 8];
#pragma unroll
        for (int nt = 0; nt < 4; nt++){
            const int c = cb + nt * 8 + lc2;
            uint32_t v00 = f2tf((r     >= c    ) ? acc1[mt][nt][0] * dec[r - c]     : 0.0f);
            uint32_t v01 = f2tf((r     >= c + 1) ? acc1[mt][nt][1] * dec[r - c - 1] : 0.0f);
            uint32_t v10 = f2tf((r + 8 >= c    ) ? acc1[mt][nt][2] * dec[r + 8 - c] : 0.0f);
            uint32_t v11 = f2tf((r + 8 >= c + 1) ? acc1[mt][nt][3] * dec[r + 7 - c] : 0.0f);
            *(uint2*)(sc + r * SD + c)       = make_uint2(v00, v01);
            *(uint2*)(sc + (r + 8) * SD + c) = make_uint2(v10, v11);
            acc2[mt][nt][0] *= e0; acc2[mt][nt][1] *= e0;
            acc2[mt][nt][2] *= e8; acc2[mt][nt][3] *= e8;
        }
    }
    CP_WAIT0();
    __syncthreads();            // V in, scores visible

    // out = qdec*(Q@S) + scores @ V  (A: raw tf32 scores; B: cvt V, natural)
    gemm_k3<false, false, true>(buf1, SD, buf2, SD, acc2, rb, cb, lane);

#pragma unroll
    for (int mt = 0; mt < 2; mt++){
        const int r = rb + mt * 16 + lr;
#pragma unroll
        for (int nt = 0; nt < 4; nt++){
            const int c = cb + nt * 8 + lc2;
            *(float2*)(o + base + (size_t)r * 128 + c)       = make_float2(acc2[mt][nt][0], acc2[mt][nt][1]);
            *(float2*)(o + base + (size_t)(r + 8) * 128 + c) = make_float2(acc2[mt][nt][2], acc2[mt][nt][3]);
        }
    }
}

extern "C" void kernel_launch(void* const* d_in, const int* in_sizes, int n_in,
                              void* d_out, int out_size) {
    const float* q = (const float*)d_in[0];
    const float* k = (const float*)d_in[1];
    const float* v = (const float*)d_in[2];
    const float* s = (const float*)d_in[3];
    float* o = (float*)d_out;

    const int sm1 = (128 + 128 * SDK + 128 * SD) * 4;       // 107,008 B  (2 CTAs/SM)
    const int sm3 = (128 + 3 * 128 * SD) * 4;               // 209,408 B
    cudaFuncSetAttribute(k_chunkKV, cudaFuncAttributeMaxDynamicSharedMemorySize, sm1);
    cudaFuncSetAttribute(k_output,  cudaFuncAttributeMaxDynamicSharedMemorySize, sm3);

    k_chunkKV<<<2048, 256, sm1>>>(k, v, s);
    k_scan<<<dim3(16, 32), 256>>>(s);
    k_output<<<1024, 512, sm3>>>(q, k, v, s, o);
}

// round 12
// speedup vs baseline: 5.3534x; 1.0293x over previous
#include <cuda_runtime.h>
#include <cstdint>

// Lightning attention, chunked-parallel, mma.sync tf32 (row.col), cp.async fills.
//   K1: C_j = (k*k_decay)^T @ v   (2048 CTAs, 64x128x128, inline cvt+scale, 2 CTAs/SM)
//   K2: exclusive decayed prefix scan g_C -> g_S (pure streams, float4; S stored tf32)
//   K3: persistent (grid=148), cross-chunk pipelined: next-Q prefetch under GEMM3,
//       next-S/K fills under o-store; per-head decay tables precomputed in smem.

#define SD  136   // smem row stride (words) for 128-col tiles (136%32==8, conflict-free)
#define SDK 72    // smem row stride for K1's 64-col k tile    (72%32==8)
#define GRIDN 148

__device__ float g_C[1024u * 16384u];   // 64 MB: chunk KV products
__device__ float g_S[1024u * 16384u];   // 64 MB: scanned exclusive states (tf32 bits)

__device__ __forceinline__ uint32_t f2tf(float x){
    uint32_t r; asm("cvt.rna.tf32.f32 %0, %1;" : "=r"(r) : "f"(x)); return r;
}
__device__ __forceinline__ uint32_t s2u(const void* p){
    uint32_t a;
    asm("{ .reg .u64 t; cvta.to.shared.u64 t, %1; cvt.u32.u64 %0, t; }" : "=r"(a) : "l"(p));
    return a;
}
__device__ __forceinline__ void cpa16(uint32_t dst, const void* src){
    asm volatile("cp.async.cg.shared.global [%0], [%1], 16;" :: "r"(dst), "l"(src));
}
#define CP_COMMIT() asm volatile("cp.async.commit_group;" ::: "memory")
#define CP_WAIT0()  asm volatile("cp.async.wait_group 0;" ::: "memory")
#define CP_WAIT1()  asm volatile("cp.async.wait_group 1;" ::: "memory")

__device__ __forceinline__ void mma8(float* c, const uint32_t* a, const uint32_t* b){
    asm volatile(
        "mma.sync.aligned.m16n8k8.row.col.f32.tf32.tf32.f32 "
        "{%0,%1,%2,%3}, {%4,%5,%6,%7}, {%8,%9}, {%0,%1,%2,%3};"
        : "+f"(c[0]), "+f"(c[1]), "+f"(c[2]), "+f"(c[3])
        : "r"(a[0]), "r"(a[1]), "r"(a[2]), "r"(a[3]), "r"(b[0]), "r"(b[1]));
}

// K1 warp GEMM: 32(m) x 32(n) x 128. A transposed-indexed + per-k scale + cvt; B natural + cvt.
__device__ __forceinline__ void gemm_k1(const float* __restrict__ A, int sa,
                                        const float* __restrict__ B, int sb,
                                        const float* __restrict__ kd,
                                        float acc[2][4][4], int rb, int cb, int lane){
    const int lr = lane >> 2, lc = lane & 3;
#pragma unroll
    for (int ks = 0; ks < 16; ks++){
        const int kc = ks * 8 + lc;
        const float s0 = kd[kc], s4 = kd[kc + 4];
        uint32_t a[2][4];
#pragma unroll
        for (int mt = 0; mt < 2; mt++){
            const int m = rb + mt * 16 + lr;
            a[mt][0] = f2tf(A[kc * sa + m] * s0);
            a[mt][1] = f2tf(A[kc * sa + m + 8] * s0);
            a[mt][2] = f2tf(A[(kc + 4) * sa + m] * s4);
            a[mt][3] = f2tf(A[(kc + 4) * sa + m + 8] * s4);
        }
#pragma unroll
        for (int nt = 0; nt < 4; nt++){
            const int n = cb + nt * 8 + lr;
            uint32_t b[2] = { f2tf(B[kc * sb + n]), f2tf(B[(kc + 4) * sb + n]) };
            mma8(acc[0][nt], a[0], b);
            mma8(acc[1][nt], a[1], b);
        }
    }
}

// K3 warp GEMM: 32x32x128. CVTA/CVTB: operand is fp32, convert inline; else raw tf32 bits.
// BT: element (k,n) at B[n*sb+k].
template<bool CVTA, bool BT, bool CVTB>
__device__ __forceinline__ void gemm_k3(const float* __restrict__ A, int sa,
                                        const float* __restrict__ B, int sb,
                                        float acc[2][4][4], int rb, int cb, int lane){
    const int lr = lane >> 2, lc = lane & 3;
#pragma unroll
    for (int ks = 0; ks < 16; ks++){
        const int kc = ks * 8 + lc;
        uint32_t a[2][4];
#pragma unroll
        for (int mt = 0; mt < 2; mt++){
            const int m = rb + mt * 16 + lr;
            float a0 = A[m * sa + kc],     a1 = A[(m + 8) * sa + kc];
            float a2 = A[m * sa + kc + 4], a3 = A[(m + 8) * sa + kc + 4];
            if (CVTA){
                a[mt][0] = f2tf(a0); a[mt][1] = f2tf(a1);
                a[mt][2] = f2tf(a2); a[mt][3] = f2tf(a3);
            } else {
                a[mt][0] = __float_as_uint(a0); a[mt][1] = __float_as_uint(a1);
                a[mt][2] = __float_as_uint(a2); a[mt][3] = __float_as_uint(a3);
            }
        }
#pragma unroll
        for (int nt = 0; nt < 4; nt++){
            const int n = cb + nt * 8 + lr;
            float b0v, b1v;
            if (BT){ b0v = B[n * sb + kc];  b1v = B[n * sb + kc + 4]; }
            else   { b0v = B[kc * sb + n];  b1v = B[(kc + 4) * sb + n]; }
            uint32_t b[2];
            if (CVTB){ b[0] = f2tf(b0v);             b[1] = f2tf(b1v); }
            else     { b[0] = __float_as_uint(b0v);  b[1] = __float_as_uint(b1v); }
            mma8(acc[0][nt], a[0], b);
            mma8(acc[1][nt], a[1], b);
        }
    }
}

__device__ __forceinline__ void fill_tile(uint32_t sdst, const float* gsrc, int gstride_f,
                                          int rowbytes, int sstride_b, int rows,
                                          int tid, int nthr){
    const int cpr = rowbytes >> 4;
    const int total = rows * cpr;
    for (int i = tid; i < total; i += nthr){
        int r = i / cpr, c = i - r * cpr;
        cpa16(sdst + r * sstride_b + c * 16, (const char*)gsrc + (size_t)r * gstride_f * 4 + c * 16);
    }
}

// ---------------- K1: C_j = (k * k_decay)^T @ v  (half of d-rows per CTA) ----------------
__global__ void __launch_bounds__(256) k_chunkKV(const float* __restrict__ k,
                                                 const float* __restrict__ v,
                                                 const float* __restrict__ s){
    extern __shared__ float sm[];
    float* kd  = sm;                    // 128 floats
    float* ksm = sm + 128;              // [tau][d-half], SDK stride
    float* vsm = ksm + 128 * SDK;       // [tau][e], SD stride
    const int tid = threadIdx.x, w = tid >> 5, lane = tid & 31;
    const int g = blockIdx.x >> 1, dh = blockIdx.x & 1, bh = g >> 5;
    const float sh = __ldg(&s[bh & 15]);
    const size_t base = ((size_t)bh * 4096 + (size_t)(g & 31) * 128) * 128;
    const uint32_t sb = s2u(sm);

    fill_tile(sb + 128 * 4, k + base + dh * 64, 128, 256, SDK * 4, 128, tid, 256);
    fill_tile(sb + (128 + 128 * SDK) * 4, v + base, 128, 512, SD * 4, 128, tid, 256);
    CP_COMMIT();
    if (tid < 128) kd[tid] = __expf(-sh * (float)(128 - tid));
    CP_WAIT0();
    __syncthreads();

    const int rb = (w & 1) * 32, cb = (w >> 1) * 32;
    float acc[2][4][4] = {};
    gemm_k1(ksm, SDK, vsm, SD, kd, acc, rb, cb, lane);

    float* C = g_C + (size_t)g * 16384 + (size_t)dh * 64 * 128;
    const int lr = lane >> 2, lc2 = (lane & 3) * 2;
#pragma unroll
    for (int mt = 0; mt < 2; mt++){
        const int r = rb + mt * 16 + lr;
#pragma unroll
        for (int nt = 0; nt < 4; nt++){
            const int c = cb + nt * 8 + lc2;
            *(float2*)(C + (size_t)r * 128 + c)       = make_float2(acc[mt][nt][0], acc[mt][nt][1]);
            *(float2*)(C + (size_t)(r + 8) * 128 + c) = make_float2(acc[mt][nt][2], acc[mt][nt][3]);
        }
    }
}

// ---------------- K2: exclusive decayed prefix scan, g_C -> g_S (tf32 out) ----------------
__global__ void __launch_bounds__(256) k_scan(const float* __restrict__ s){
    const int bh = blockIdx.y;
    const int e4 = blockIdx.x * 256 + threadIdx.x;
    const float lamB = __expf(-__ldg(&s[bh & 15]) * 128.0f);
    const float4* __restrict__ src = (const float4*)(g_C + (size_t)bh * 32 * 16384) + e4;
    uint4* __restrict__ dst        = (uint4*)(g_S + (size_t)bh * 32 * 16384) + e4;

    float4 val = make_float4(0.f, 0.f, 0.f, 0.f);
    float4 c = src[0];
#pragma unroll
    for (int j = 0; j < 32; j++){
        float4 cn = (j < 31) ? src[(j + 1) * 4096] : make_float4(0.f, 0.f, 0.f, 0.f);
        dst[j * 4096] = make_uint4(f2tf(val.x), f2tf(val.y), f2tf(val.z), f2tf(val.w));
        val.x = lamB * val.x + c.x;
        val.y = lamB * val.y + c.y;
        val.z = lamB * val.z + c.z;
        val.w = lamB * val.w + c.w;
        c = cn;
    }
}

// ---------------- K3: persistent output, cross-chunk pipelined ----------------
__global__ void __launch_bounds__(512) k_output(const float* __restrict__ q,
                                                const float* __restrict__ k,
                                                const float* __restrict__ v,
                                                const float* __restrict__ s,
                                                float* __restrict__ o){
    extern __shared__ float sm[];
    float* decs = sm;                    // 16 heads x 128 decay values
    float* Qs   = sm + 2048;             // Q (fp32, cvt inline)
    float* buf1 = Qs + 128 * SD;         // K (fp32), later scores (tf32 bits)
    float* buf2 = buf1 + 128 * SD;       // S (tf32 bits), later V (fp32)
    const int tid = threadIdx.x, w = tid >> 5, lane = tid & 31;
    const uint32_t sb = s2u(sm);
    const uint32_t oQ = sb + 8192, o1 = oQ + 128 * SD * 4, o2 = o1 + 128 * SD * 4;
    const int rb = (w >> 2) * 32, cb = (w & 3) * 32;
    const int lr = lane >> 2, lc2 = (lane & 3) * 2;

    // per-head decay tables, once
    for (int i = tid; i < 2048; i += 512){
        int h = i >> 7, t = i & 127;
        decs[i] = __expf(-__ldg(&s[h]) * (float)t);
    }

    int g = blockIdx.x;
    if (g < 1024){
        const size_t b0 = ((size_t)(g >> 5) * 4096 + (size_t)(g & 31) * 128) * 128;
        fill_tile(oQ, q + b0, 128, 512, SD * 4, 128, tid, 512); CP_COMMIT();  // Q
        fill_tile(o2, g_S + (size_t)g * 16384, 128, 512, SD * 4, 128, tid, 512); CP_COMMIT(); // S
        fill_tile(o1, k + b0, 128, 512, SD * 4, 128, tid, 512); CP_COMMIT();  // K
    }

    for (; g < 1024; g += GRIDN){
        const int bh = g >> 5;
        const float* dec = decs + ((bh & 15) << 7);
        const size_t base = ((size_t)bh * 4096 + (size_t)(g & 31) * 128) * 128;
        const int gn = g + GRIDN;
        const size_t basen = (gn < 1024)
            ? ((size_t)(gn >> 5) * 4096 + (size_t)(gn & 31) * 128) * 128 : 0;

        CP_WAIT1();                 // Q + S arrived (K still in flight)
        __syncthreads();

        float acc2[2][4][4] = {};   // inter = Q @ S
        gemm_k3<true, false, false>(Qs, SD, buf2, SD, acc2, rb, cb, lane);

        CP_WAIT0();                 // K arrived
        __syncthreads();            // all warps done reading buf2 (S)

        fill_tile(o2, v + base, 128, 512, SD * 4, 128, tid, 512);
        CP_COMMIT();                // V (lands under GEMM1 + epilogue)

        float acc1[2][4][4] = {};   // scores = Q @ K^T
        gemm_k3<true, true, true>(Qs, SD, buf1, SD, acc1, rb, cb, lane);
        __syncthreads();            // done reading buf1 (K) and Qs (Q)

        // prefetch next chunk's Q into Qs (dead now); lands under epilogue+GEMM3
        if (gn < 1024) fill_tile(oQ, q + basen, 128, 512, SD * 4, 128, tid, 512);
        CP_COMMIT();                // nextQ

        // epilogue: mask+decay scores -> buf1 as tf32 bits; pre-scale inter by q_decay
        uint32_t* sc = (uint32_t*)buf1;
#pragma unroll
        for (int mt = 0; mt < 2; mt++){
            const int r = rb + mt * 16 + lr;
            const float e0 = dec[r], e8 = dec[r + 8];
#pragma unroll
            for (int nt = 0; nt < 4; nt++){
                const int c = cb + nt * 8 + lc2;
                uint32_t v00 = f2tf((r     >= c    ) ? acc1[mt][nt][0] * dec[r - c]     : 0.0f);
                uint32_t v01 = f2tf((r     >= c + 1) ? acc1[mt][nt][1] * dec[r - c - 1] : 0.0f);
                uint32_t v10 = f2tf((r + 8 >= c    ) ? acc1[mt][nt][2] * dec[r + 8 - c] : 0.0f);
                uint32_t v11 = f2tf((r + 8 >= c + 1) ? acc1[mt][nt][3] * dec[r + 7 - c] : 0.0f);
                *(uint2*)(sc + r * SD + c)       = make_uint2(v00, v01);
                *(uint2*)(sc + (r + 8) * SD + c) = make_uint2(v10, v11);
                acc2[mt][nt][0] *= e0; acc2[mt][nt][1] *= e0;
                acc2[mt][nt][2] *= e8; acc2[mt][nt][3] *= e8;
            }
        }

        CP_WAIT1();                 // V arrived (nextQ still in flight)
        __syncthreads();            // scores visible, V ready

        // out = qdec*(Q@S) + scores @ V
        gemm_k3<false, false, true>(buf1, SD, buf2, SD, acc2, rb, cb, lane);
        __syncthreads();            // all warps done with buf1 (scores), buf2 (V)

        // next chunk's S and K fills: overlap with o-store below
        if (gn < 1024) fill_tile(o2, g_S + (size_t)gn * 16384, 128, 512, SD * 4, 128, tid, 512);
        CP_COMMIT();                // nextS
        if (gn < 1024) fill_tile(o1, k + basen, 128, 512, SD * 4, 128, tid, 512);
        CP_COMMIT();                // nextK

#pragma unroll
        for (int mt = 0; mt < 2; mt++){
            const int r = rb + mt * 16 + lr;
#pragma unroll
            for (int nt = 0; nt < 4; nt++){
                const int c = cb + nt * 8 + lc2;
                *(float2*)(o + base + (size_t)r * 128 + c)       = make_float2(acc2[mt][nt][0], acc2[mt][nt][1]);
                *(float2*)(o + base + (size_t)(r + 8) * 128 + c) = make_float2(acc2[mt][nt][2], acc2[mt][nt][3]);
            }
        }
    }
}

extern "C" void kernel_launch(void* const* d_in, const int* in_sizes, int n_in,
                              void* d_out, int out_size) {
    const float* q = (const float*)d_in[0];
    const float* k = (const float*)d_in[1];
    const float* v = (const float*)d_in[2];
    const float* s = (const float*)d_in[3];
    float* o = (float*)d_out;

    const int sm1 = (128 + 128 * SDK + 128 * SD) * 4;       // 107,008 B  (2 CTAs/SM)
    const int sm3 = 8192 + 3 * 128 * SD * 4;                // 217,088 B
    cudaFuncSetAttribute(k_chunkKV, cudaFuncAttributeMaxDynamicSharedMemorySize, sm1);
    cudaFuncSetAttribute(k_output,  cudaFuncAttributeMaxDynamicSharedMemorySize, sm3);

    k_chunkKV<<<2048, 256, sm1>>>(k, v, s);
    k_scan<<<dim3(16, 32), 256>>>(s);
    k_output<<<GRIDN, 512, sm3>>>(q, k, v, s, o);
}